// round 3
// baseline (speedup 1.0000x reference)
#include <cuda_runtime.h>
#include <cstdint>

// ---------------------------------------------------------------------------
// Problem constants (fixed dataset): N=50000 nodes, E=800000 edges,
// IN=128, L1: 4 heads x 64 = 256, L2: 1 head x 64.
// edge_index is int32 (JAX x64-disabled downgrades jnp.int64 -> int32).
// ---------------------------------------------------------------------------
#define NMAX 50000

// Scratch (static device globals -- no allocation allowed).
__device__ __align__(16) float g_h1  [NMAX * 256];   // layer1 linear output [N,4,64]
__device__ __align__(16) float g_out1[NMAX * 256];   // layer1 aggregation accumulator
__device__ __align__(16) float g_h2  [NMAX * 64];    // layer2 linear output
__device__ __align__(16) float g_out2[NMAX * 64];    // layer2 aggregation accumulator
__device__ __align__(16) float g_as1 [NMAX * 4];     // a_src layer1 [N,4]
__device__ __align__(16) float g_ad1 [NMAX * 4];     // a_dst layer1 [N,4]
__device__ __align__(16) float g_dn1 [NMAX * 4];     // softmax denom layer1
__device__ __align__(16) float g_as2 [NMAX];
__device__ __align__(16) float g_ad2 [NMAX];
__device__ __align__(16) float g_dn2 [NMAX];

// ---------------------------------------------------------------------------
// Helpers
// ---------------------------------------------------------------------------
__device__ __forceinline__ void red_add_v4(float* addr, float4 v) {
    asm volatile("red.global.add.v4.f32 [%0], {%1,%2,%3,%4};"
                 :: "l"(addr), "f"(v.x), "f"(v.y), "f"(v.z), "f"(v.w) : "memory");
}
__device__ __forceinline__ void red_add_v2(float* addr, float2 v) {
    asm volatile("red.global.add.v2.f32 [%0], {%1,%2};"
                 :: "l"(addr), "f"(v.x), "f"(v.y) : "memory");
}
__device__ __forceinline__ float lrelu(float x) { return x > 0.f ? x : 0.2f * x; }
__device__ __forceinline__ float elu(float x)   { return x > 0.f ? x : expm1f(x); }

// ---------------------------------------------------------------------------
// Zero the accumulators (fresh every call; graph replays depend on it)
// ---------------------------------------------------------------------------
__global__ void zero_kernel(float* o1, float* o2, float* d1, float* d2, int N) {
    int i = blockIdx.x * blockDim.x + threadIdx.x;
    int stride = gridDim.x * blockDim.x;
    int n1 = N * 256, n2 = N * 64, n3 = N * 4;
    for (int j = i; j < n1; j += stride) o1[j] = 0.f;
    for (int j = i; j < n2; j += stride) o2[j] = 0.f;
    for (int j = i; j < n3; j += stride) d1[j] = 0.f;
    for (int j = i; j < N;  j += stride) d2[j] = 0.f;
}

// ---------------------------------------------------------------------------
// Register-blocked SGEMM: C[M,Nc] = A[M,K] @ B[K,Nc], all row-major fp32.
// BM=128, BN=64, BK=16, TM=8, TN=4, 256 threads.
// ---------------------------------------------------------------------------
template <int BM, int BN, int BK, int TM, int TN>
__global__ __launch_bounds__(256) void sgemm_kernel(
    int M, int Nc, int K,
    const float* __restrict__ A, const float* __restrict__ B, float* __restrict__ C)
{
    __shared__ float As[BK][BM];
    __shared__ float Bs[BK][BN];

    const int tid  = threadIdx.x;
    const int bx   = blockIdx.x;
    const int by   = blockIdx.y;
    const int tcol = tid % (BN / TN);   // 0..15
    const int trow = tid / (BN / TN);   // 0..15

    float acc[TM][TN];
#pragma unroll
    for (int i = 0; i < TM; i++)
#pragma unroll
        for (int j = 0; j < TN; j++) acc[i][j] = 0.f;

    const int aRow = tid / (BK / 4);          // 0..63
    const int aCol = (tid % (BK / 4)) * 4;    // 0,4,8,12
    const int bRow = tid / (BN / 4);          // 0..15
    const int bCol = (tid % (BN / 4)) * 4;    // 0..60

    const float* Ab = A + (size_t)by * BM * K;

    for (int k0 = 0; k0 < K; k0 += BK) {
        // Load A tile (BM x BK), stored transposed in smem
#pragma unroll
        for (int i = 0; i < BM; i += 64) {
            int r  = aRow + i;
            int gr = by * BM + r;
            float4 v = (gr < M)
                ? *(const float4*)(Ab + (size_t)r * K + k0 + aCol)
                : make_float4(0.f, 0.f, 0.f, 0.f);
            As[aCol + 0][r] = v.x;
            As[aCol + 1][r] = v.y;
            As[aCol + 2][r] = v.z;
            As[aCol + 3][r] = v.w;
        }
        // Load B tile (BK x BN): exactly one float4 per thread
        {
            float4 v = *(const float4*)(B + (size_t)(k0 + bRow) * Nc + bx * BN + bCol);
            *(float4*)&Bs[bRow][bCol] = v;
        }
        __syncthreads();

#pragma unroll
        for (int kk = 0; kk < BK; kk++) {
            float ra[TM], rb[TN];
#pragma unroll
            for (int i = 0; i < TM; i++) ra[i] = As[kk][trow * TM + i];
#pragma unroll
            for (int j = 0; j < TN; j++) rb[j] = Bs[kk][tcol * TN + j];
#pragma unroll
            for (int i = 0; i < TM; i++)
#pragma unroll
                for (int j = 0; j < TN; j++) acc[i][j] += ra[i] * rb[j];
        }
        __syncthreads();
    }

#pragma unroll
    for (int i = 0; i < TM; i++) {
        int gr = by * BM + trow * TM + i;
        if (gr < M) {
            float4 v = make_float4(acc[i][0], acc[i][1], acc[i][2], acc[i][3]);
            *(float4*)(C + (size_t)gr * Nc + bx * BN + tcol * TN) = v;
        }
    }
}

// ---------------------------------------------------------------------------
// Attention scalars layer1: a_src[n,h] = dot(h1[n,h,:], att_src[h,:]) etc.
// One warp per node; att vectors [4,64] flattened match the 256-wide row.
// ---------------------------------------------------------------------------
__global__ void att1_kernel(const float* __restrict__ h1,
                            const float* __restrict__ att_s,
                            const float* __restrict__ att_d,
                            float* __restrict__ asrc, float* __restrict__ adst, int N)
{
    int w    = (blockIdx.x * blockDim.x + threadIdx.x) >> 5;
    int lane = threadIdx.x & 31;
    if (w >= N) return;
    const float* row = h1 + (size_t)w * 256;
    float s[4] = {0.f, 0.f, 0.f, 0.f};
    float d[4] = {0.f, 0.f, 0.f, 0.f};
#pragma unroll
    for (int k = 0; k < 8; k++) {
        int idx = lane + k * 32;
        float v = row[idx];
        s[k >> 1] += v * att_s[idx];
        d[k >> 1] += v * att_d[idx];
    }
#pragma unroll
    for (int h = 0; h < 4; h++) {
        float a = s[h], b = d[h];
#pragma unroll
        for (int off = 16; off; off >>= 1) {
            a += __shfl_xor_sync(0xffffffffu, a, off);
            b += __shfl_xor_sync(0xffffffffu, b, off);
        }
        if (lane == 0) { asrc[w * 4 + h] = a; adst[w * 4 + h] = b; }
    }
}

__global__ void att2_kernel(const float* __restrict__ h2,
                            const float* __restrict__ att_s,
                            const float* __restrict__ att_d,
                            float* __restrict__ asrc, float* __restrict__ adst, int N)
{
    int w    = (blockIdx.x * blockDim.x + threadIdx.x) >> 5;
    int lane = threadIdx.x & 31;
    if (w >= N) return;
    const float* row = h2 + (size_t)w * 64;
    float v0 = row[lane], v1 = row[lane + 32];
    float a = v0 * att_s[lane] + v1 * att_s[lane + 32];
    float b = v0 * att_d[lane] + v1 * att_d[lane + 32];
#pragma unroll
    for (int off = 16; off; off >>= 1) {
        a += __shfl_xor_sync(0xffffffffu, a, off);
        b += __shfl_xor_sync(0xffffffffu, b, off);
    }
    if (lane == 0) { asrc[w] = a; adst[w] = b; }
}

// ---------------------------------------------------------------------------
// Edge pass A (layer1): accumulate softmax denominator per (dst, head).
// Shift-free softmax: logits bounded, self-loop guarantees denom >> 1e-16.
// edge_index layout: ei[0:E] = src, ei[E:2E] = dst (int32).
// ---------------------------------------------------------------------------
__global__ void edge_denom1(const int* __restrict__ ei,
                            const float* __restrict__ asrc, const float* __restrict__ adst,
                            float* __restrict__ den, int E, int N)
{
    int e = blockIdx.x * blockDim.x + threadIdx.x;
    int ET = E + N;
    if (e >= ET) return;
    int s, d;
    if (e < E) { s = ei[e]; d = ei[E + e]; }
    else       { s = e - E; d = s; }
    float4 a = *(const float4*)(asrc + (size_t)s * 4);
    float4 b = *(const float4*)(adst + (size_t)d * 4);
    float4 w;
    w.x = __expf(lrelu(a.x + b.x));
    w.y = __expf(lrelu(a.y + b.y));
    w.z = __expf(lrelu(a.z + b.z));
    w.w = __expf(lrelu(a.w + b.w));
    red_add_v4(den + (size_t)d * 4, w);
}

// Edge pass B (layer1): one warp per edge, lane covers 8 of 256 channels.
__global__ void edge_scatter1(const int* __restrict__ ei,
                              const float* __restrict__ h1,
                              const float* __restrict__ asrc, const float* __restrict__ adst,
                              const float* __restrict__ den,
                              float* __restrict__ out, int E, int N)
{
    int gw   = (blockIdx.x * blockDim.x + threadIdx.x) >> 5;
    int lane = threadIdx.x & 31;
    int ET = E + N;
    if (gw >= ET) return;
    int s, d;
    if (gw < E) { s = __ldg(ei + gw); d = __ldg(ei + E + gw); }
    else        { s = gw - E; d = s; }
    int head = lane >> 3;
    float a = __ldg(asrc + (size_t)s * 4 + head) + __ldg(adst + (size_t)d * 4 + head);
    a = lrelu(a);
    float alpha = __expf(a) / (__ldg(den + (size_t)d * 4 + head) + 1e-16f);

    const float4* hp = (const float4*)(h1 + (size_t)s * 256 + lane * 8);
    float4 v0 = __ldg(hp), v1 = __ldg(hp + 1);
    v0.x *= alpha; v0.y *= alpha; v0.z *= alpha; v0.w *= alpha;
    v1.x *= alpha; v1.y *= alpha; v1.z *= alpha; v1.w *= alpha;
    float* op = out + (size_t)d * 256 + lane * 8;
    red_add_v4(op, v0);
    red_add_v4(op + 4, v1);
}

// Bias + ELU in place on [N,256] (float4 granularity)
__global__ void bias_elu1(float* __restrict__ data, const float* __restrict__ bias, int N)
{
    int g = blockIdx.x * blockDim.x + threadIdx.x;   // over N*64 float4s
    if (g >= N * 64) return;
    float4 v = ((float4*)data)[g];
    int c4 = g & 63;                                 // (256/4)-1
    float4 b = ((const float4*)bias)[c4];
    v.x = elu(v.x + b.x);
    v.y = elu(v.y + b.y);
    v.z = elu(v.z + b.z);
    v.w = elu(v.w + b.w);
    ((float4*)data)[g] = v;
}

// Edge passes layer2 (1 head, 64 channels)
__global__ void edge_denom2(const int* __restrict__ ei,
                            const float* __restrict__ asrc, const float* __restrict__ adst,
                            float* __restrict__ den, int E, int N)
{
    int e = blockIdx.x * blockDim.x + threadIdx.x;
    int ET = E + N;
    if (e >= ET) return;
    int s, d;
    if (e < E) { s = ei[e]; d = ei[E + e]; }
    else       { s = e - E; d = s; }
    float w = __expf(lrelu(asrc[s] + adst[d]));
    atomicAdd(den + d, w);
}

__global__ void edge_scatter2(const int* __restrict__ ei,
                              const float* __restrict__ h2,
                              const float* __restrict__ asrc, const float* __restrict__ adst,
                              const float* __restrict__ den,
                              float* __restrict__ out, int E, int N)
{
    int gw   = (blockIdx.x * blockDim.x + threadIdx.x) >> 5;
    int lane = threadIdx.x & 31;
    int ET = E + N;
    if (gw >= ET) return;
    int s, d;
    if (gw < E) { s = __ldg(ei + gw); d = __ldg(ei + E + gw); }
    else        { s = gw - E; d = s; }
    float a = lrelu(__ldg(asrc + s) + __ldg(adst + d));
    float alpha = __expf(a) / (__ldg(den + d) + 1e-16f);
    float2 v = __ldg((const float2*)(h2 + (size_t)s * 64) + lane);
    v.x *= alpha; v.y *= alpha;
    red_add_v2(out + (size_t)d * 64 + lane * 2, v);
}

// Final: h = elu(out2 + b2); scores = h @ Ws + bs. One warp per node.
__global__ void final_kernel(const float* __restrict__ b2, const float* __restrict__ Ws,
                             const float* __restrict__ bs, const float* __restrict__ out2,
                             float* __restrict__ out, int N)
{
    int w    = (blockIdx.x * blockDim.x + threadIdx.x) >> 5;
    int lane = threadIdx.x & 31;
    if (w >= N) return;
    float v0 = out2[(size_t)w * 64 + lane]      + b2[lane];
    float v1 = out2[(size_t)w * 64 + 32 + lane] + b2[32 + lane];
    v0 = elu(v0); v1 = elu(v1);
    out[(size_t)w * 64 + lane]      = v0;
    out[(size_t)w * 64 + 32 + lane] = v1;
    float sc = v0 * Ws[lane] + v1 * Ws[lane + 32];
#pragma unroll
    for (int off = 16; off; off >>= 1) sc += __shfl_xor_sync(0xffffffffu, sc, off);
    if (lane == 0) out[(size_t)N * 64 + w] = sc + bs[0];
}

// ---------------------------------------------------------------------------
// Launch
// ---------------------------------------------------------------------------
extern "C" void kernel_launch(void* const* d_in, const int* in_sizes, int n_in,
                              void* d_out, int out_size)
{
    const float* x   = (const float*)d_in[0];
    const int*   ei  = (const int*)d_in[1];      // int32 edge_index [2,E]
    const float* W1  = (const float*)d_in[2];
    const float* as1 = (const float*)d_in[3];
    const float* ad1 = (const float*)d_in[4];
    const float* b1  = (const float*)d_in[5];
    const float* W2  = (const float*)d_in[6];
    const float* as2 = (const float*)d_in[7];
    const float* ad2 = (const float*)d_in[8];
    const float* b2  = (const float*)d_in[9];
    const float* Ws  = (const float*)d_in[10];
    const float* bs  = (const float*)d_in[11];
    float*       out = (float*)d_out;

    const int N  = in_sizes[0] / 128;
    const int E  = in_sizes[1] / 2;
    const int ET = E + N;

    float *h1, *o1, *h2, *o2, *as1p, *ad1p, *d1p, *as2p, *ad2p, *d2p;
    cudaGetSymbolAddress((void**)&h1,   g_h1);
    cudaGetSymbolAddress((void**)&o1,   g_out1);
    cudaGetSymbolAddress((void**)&h2,   g_h2);
    cudaGetSymbolAddress((void**)&o2,   g_out2);
    cudaGetSymbolAddress((void**)&as1p, g_as1);
    cudaGetSymbolAddress((void**)&ad1p, g_ad1);
    cudaGetSymbolAddress((void**)&d1p,  g_dn1);
    cudaGetSymbolAddress((void**)&as2p, g_as2);
    cudaGetSymbolAddress((void**)&ad2p, g_ad2);
    cudaGetSymbolAddress((void**)&d2p,  g_dn2);

    zero_kernel<<<4096, 256>>>(o1, o2, d1p, d2p, N);

    // Layer 1
    sgemm_kernel<128, 64, 16, 8, 4>
        <<<dim3(256 / 64, (N + 127) / 128), 256>>>(N, 256, 128, x, W1, h1);
    att1_kernel<<<(N * 32 + 255) / 256, 256>>>(h1, as1, ad1, as1p, ad1p, N);
    edge_denom1<<<(ET + 255) / 256, 256>>>(ei, as1p, ad1p, d1p, E, N);
    edge_scatter1<<<(ET * 32 + 255) / 256, 256>>>(ei, h1, as1p, ad1p, d1p, o1, E, N);
    bias_elu1<<<(N * 64 + 255) / 256, 256>>>(o1, b1, N);

    // Layer 2
    sgemm_kernel<128, 64, 16, 8, 4>
        <<<dim3(1, (N + 127) / 128), 256>>>(N, 64, 256, o1, W2, h2);
    att2_kernel<<<(N * 32 + 255) / 256, 256>>>(h2, as2, ad2, as2p, ad2p, N);
    edge_denom2<<<(ET + 255) / 256, 256>>>(ei, as2p, ad2p, d2p, E, N);
    edge_scatter2<<<(ET * 32 + 255) / 256, 256>>>(ei, h2, as2p, ad2p, d2p, o2, E, N);

    // Epilogue: h_final + scores
    final_kernel<<<(N * 32 + 255) / 256, 256>>>(b2, Ws, bs, o2, out, N);
}

// round 4
// speedup vs baseline: 1.4984x; 1.4984x over previous
#include <cuda_runtime.h>
#include <cstdint>

// ---------------------------------------------------------------------------
// Fixed dataset: N=50000, E=800000, IN=128, L1: 4 heads x 64, L2: 1 head x 64.
// edge_index is int32: ei[0:E]=src, ei[E:2E]=dst. Self-loops handled in-warp.
// ---------------------------------------------------------------------------
#define NMAX 50000
#define EMAX 810000

__device__ __align__(16) float g_h1 [NMAX * 256];  // layer1 linear output
__device__ __align__(16) float g_hm [NMAX * 256];  // layer1 GAT output (elu'd) = layer2 input
__device__ __align__(16) float g_h2 [NMAX * 64];   // layer2 linear output
__device__ __align__(16) float g_as1[NMAX * 4];
__device__ __align__(16) float g_ad1[NMAX * 4];
__device__ __align__(16) float g_as2[NMAX];
__device__ __align__(16) float g_ad2[NMAX];
// CSR by dst
__device__ int g_cnt [NMAX];
__device__ int g_rp  [NMAX + 1];
__device__ int g_cur [NMAX];
__device__ int g_col [EMAX];

__device__ __forceinline__ float lrelu(float x) { return x > 0.f ? x : 0.2f * x; }
__device__ __forceinline__ float elu(float x)   { return x > 0.f ? x : expm1f(x); }

// ---------------------------------------------------------------------------
// CSR build
// ---------------------------------------------------------------------------
__global__ void zero_cnt(int* cnt, int N) {
    int i = blockIdx.x * blockDim.x + threadIdx.x;
    if (i < N) cnt[i] = 0;
}

__global__ void count_kernel(const int* __restrict__ ei, int* cnt, int E) {
    int e = blockIdx.x * blockDim.x + threadIdx.x;
    if (e < E) atomicAdd(cnt + ei[E + e], 1);
}

// Single-block exclusive scan (N <= 1024*64)
__global__ void scan_kernel(const int* __restrict__ cnt, int* rp, int* cur, int N) {
    __shared__ int sums[1024];
    int t = threadIdx.x;
    int C = (N + 1023) / 1024;
    int b0 = t * C, b1 = min(N, b0 + C);
    int s = 0;
    for (int i = b0; i < b1; i++) s += cnt[i];
    sums[t] = s;
    __syncthreads();
    for (int off = 1; off < 1024; off <<= 1) {
        int v = (t >= off) ? sums[t - off] : 0;
        __syncthreads();
        sums[t] += v;
        __syncthreads();
    }
    int run = (t == 0) ? 0 : sums[t - 1];
    for (int i = b0; i < b1; i++) { rp[i] = run; cur[i] = run; run += cnt[i]; }
    if (b0 < N && b1 == N) rp[N] = run;
}

__global__ void fill_kernel(const int* __restrict__ ei, int* cur, int* col, int E) {
    int e = blockIdx.x * blockDim.x + threadIdx.x;
    if (e >= E) return;
    int d = ei[E + e];
    int pos = atomicAdd(cur + d, 1);
    col[pos] = ei[e];
}

// ---------------------------------------------------------------------------
// SGEMM: C[M,Nc] = A[M,K] @ B[K,Nc], row-major fp32. 256 threads.
// Requires: K%BK==0, Nc%BN==0, BM%TM==0, BN%TN==0, (BM/TM)*(BN/TN)==256.
// ---------------------------------------------------------------------------
template <int BM, int BN, int BK, int TM, int TN>
__global__ __launch_bounds__(256) void sgemm_kernel(
    int M, int Nc, int K,
    const float* __restrict__ A, const float* __restrict__ B, float* __restrict__ C)
{
    __shared__ float As[BK][BM];
    __shared__ float Bs[BK][BN];

    const int tid  = threadIdx.x;
    const int bx   = blockIdx.x;
    const int by   = blockIdx.y;
    const int tcol = tid % (BN / TN);
    const int trow = tid / (BN / TN);

    float acc[TM][TN];
#pragma unroll
    for (int i = 0; i < TM; i++)
#pragma unroll
        for (int j = 0; j < TN; j++) acc[i][j] = 0.f;

    const float* Ab = A + (size_t)by * BM * K;

    for (int k0 = 0; k0 < K; k0 += BK) {
        // A tile: BM x BK, stored transposed
#pragma unroll
        for (int i = tid; i < BM * BK / 4; i += 256) {
            int r  = i / (BK / 4);
            int c  = (i % (BK / 4)) * 4;
            int gr = by * BM + r;
            float4 v = (gr < M)
                ? *(const float4*)(Ab + (size_t)r * K + k0 + c)
                : make_float4(0.f, 0.f, 0.f, 0.f);
            As[c + 0][r] = v.x; As[c + 1][r] = v.y;
            As[c + 2][r] = v.z; As[c + 3][r] = v.w;
        }
        // B tile: BK x BN
#pragma unroll
        for (int i = tid; i < BK * BN / 4; i += 256) {
            int r = i / (BN / 4);
            int c = (i % (BN / 4)) * 4;
            *(float4*)&Bs[r][c] = *(const float4*)(B + (size_t)(k0 + r) * Nc + bx * BN + c);
        }
        __syncthreads();

#pragma unroll
        for (int kk = 0; kk < BK; kk++) {
            float ra[TM], rb[TN];
#pragma unroll
            for (int i = 0; i < TM; i += 4) *(float4*)&ra[i] = *(float4*)&As[kk][trow * TM + i];
#pragma unroll
            for (int j = 0; j < TN; j += 4) *(float4*)&rb[j] = *(float4*)&Bs[kk][tcol * TN + j];
#pragma unroll
            for (int i = 0; i < TM; i++)
#pragma unroll
                for (int j = 0; j < TN; j++) acc[i][j] += ra[i] * rb[j];
        }
        __syncthreads();
    }

#pragma unroll
    for (int i = 0; i < TM; i++) {
        int gr = by * BM + trow * TM + i;
        if (gr < M) {
#pragma unroll
            for (int j = 0; j < TN; j += 4) {
                float4 v = make_float4(acc[i][j], acc[i][j+1], acc[i][j+2], acc[i][j+3]);
                *(float4*)(C + (size_t)gr * Nc + bx * BN + tcol * TN + j) = v;
            }
        }
    }
}

// ---------------------------------------------------------------------------
// Attention scalar kernels
// ---------------------------------------------------------------------------
__global__ void att1_kernel(const float* __restrict__ h1,
                            const float* __restrict__ att_s,
                            const float* __restrict__ att_d,
                            float* __restrict__ asrc, float* __restrict__ adst, int N)
{
    int w    = (blockIdx.x * blockDim.x + threadIdx.x) >> 5;
    int lane = threadIdx.x & 31;
    if (w >= N) return;
    const float* row = h1 + (size_t)w * 256;
    float s[4] = {0.f,0.f,0.f,0.f}, d[4] = {0.f,0.f,0.f,0.f};
#pragma unroll
    for (int k = 0; k < 8; k++) {
        int idx = lane + k * 32;
        float v = row[idx];
        s[k >> 1] += v * att_s[idx];
        d[k >> 1] += v * att_d[idx];
    }
#pragma unroll
    for (int h = 0; h < 4; h++) {
        float a = s[h], b = d[h];
#pragma unroll
        for (int off = 16; off; off >>= 1) {
            a += __shfl_xor_sync(0xffffffffu, a, off);
            b += __shfl_xor_sync(0xffffffffu, b, off);
        }
        if (lane == 0) { asrc[w * 4 + h] = a; adst[w * 4 + h] = b; }
    }
}

__global__ void att2_kernel(const float* __restrict__ h2,
                            const float* __restrict__ att_s,
                            const float* __restrict__ att_d,
                            float* __restrict__ asrc, float* __restrict__ adst, int N)
{
    int w    = (blockIdx.x * blockDim.x + threadIdx.x) >> 5;
    int lane = threadIdx.x & 31;
    if (w >= N) return;
    const float* row = h2 + (size_t)w * 64;
    float v0 = row[lane], v1 = row[lane + 32];
    float a = v0 * att_s[lane] + v1 * att_s[lane + 32];
    float b = v0 * att_d[lane] + v1 * att_d[lane + 32];
#pragma unroll
    for (int off = 16; off; off >>= 1) {
        a += __shfl_xor_sync(0xffffffffu, a, off);
        b += __shfl_xor_sync(0xffffffffu, b, off);
    }
    if (lane == 0) { asrc[w] = a; adst[w] = b; }
}

// ---------------------------------------------------------------------------
// Layer-1 GAT gather: one warp per dst node. Computes softmax denom in-warp,
// accumulates messages in registers, writes elu(out + b1) once. No atomics.
// ---------------------------------------------------------------------------
#define WCAP 128   // cached edge weights per warp (deg > WCAP -> recompute path)

__global__ __launch_bounds__(256) void gather1_kernel(
    const int* __restrict__ rp, const int* __restrict__ col,
    const float* __restrict__ h1,
    const float* __restrict__ asrc, const float* __restrict__ adst,
    const float* __restrict__ bias, float* __restrict__ out, int N)
{
    __shared__ float s_w[8][WCAP * 4];
    int warp = threadIdx.x >> 5, lane = threadIdx.x & 31;
    int d = blockIdx.x * 8 + warp;
    if (d >= N) return;

    int beg = rp[d];
    int deg = rp[d + 1] - beg;
    int hme = lane & 3;                         // head this lane accumulates denom for
    float ad_hme = __ldg(adst + (size_t)d * 4 + hme);

    // Phase A: per-(edge,head) weights, lane-strided; cache first WCAP edges
    float pden = 0.f;
    int npairs = deg * 4;
    for (int idx = lane; idx < npairs; idx += 32) {
        int e = idx >> 2;                       // h == idx&3 == hme (stride 32 preserves &3)
        int s = __ldg(col + beg + e);
        float w = __expf(lrelu(__ldg(asrc + (size_t)s * 4 + hme) + ad_hme));
        if (e < WCAP) s_w[warp][idx] = w;
        pden += w;
    }
    // reduce over the 8 lanes sharing hme
    pden += __shfl_xor_sync(0xffffffffu, pden, 4);
    pden += __shfl_xor_sync(0xffffffffu, pden, 8);
    pden += __shfl_xor_sync(0xffffffffu, pden, 16);
    // self-loop weight (same value across the 8 lanes of a head group)
    float w_self = __expf(lrelu(__ldg(asrc + (size_t)d * 4 + hme) + ad_hme));
    float inv_den = 1.f / (pden + w_self + 1e-16f);
    __syncwarp();

    // Phase B: lane covers channels [lane*8, lane*8+8) -> head = lane>>3
    int head = lane >> 3;
    float inv_h   = __shfl_sync(0xffffffffu, inv_den, head);
    float aself_h = __shfl_sync(0xffffffffu, w_self,  head) * inv_h;
    float ad_head = __shfl_sync(0xffffffffu, ad_hme,  head);

    float acc[8];
    {   // self-loop message
        const float4* hp = (const float4*)(h1 + (size_t)d * 256 + lane * 8);
        float4 v0 = __ldg(hp), v1 = __ldg(hp + 1);
        acc[0]=aself_h*v0.x; acc[1]=aself_h*v0.y; acc[2]=aself_h*v0.z; acc[3]=aself_h*v0.w;
        acc[4]=aself_h*v1.x; acc[5]=aself_h*v1.y; acc[6]=aself_h*v1.z; acc[7]=aself_h*v1.w;
    }
    for (int e = 0; e < deg; e++) {
        int s = __ldg(col + beg + e);
        float w = (e < WCAP) ? s_w[warp][e * 4 + head]
                             : __expf(lrelu(__ldg(asrc + (size_t)s * 4 + head) + ad_head));
        float alpha = w * inv_h;
        const float4* hp = (const float4*)(h1 + (size_t)s * 256 + lane * 8);
        float4 v0 = __ldg(hp), v1 = __ldg(hp + 1);
        acc[0]+=alpha*v0.x; acc[1]+=alpha*v0.y; acc[2]+=alpha*v0.z; acc[3]+=alpha*v0.w;
        acc[4]+=alpha*v1.x; acc[5]+=alpha*v1.y; acc[6]+=alpha*v1.z; acc[7]+=alpha*v1.w;
    }
    // epilogue: bias + elu, single write
    const float4* bp = (const float4*)(bias + lane * 8);
    float4 b0 = __ldg(bp), b1v = __ldg(bp + 1);
    float4 o0, o1;
    o0.x=elu(acc[0]+b0.x);  o0.y=elu(acc[1]+b0.y);  o0.z=elu(acc[2]+b0.z);  o0.w=elu(acc[3]+b0.w);
    o1.x=elu(acc[4]+b1v.x); o1.y=elu(acc[5]+b1v.y); o1.z=elu(acc[6]+b1v.z); o1.w=elu(acc[7]+b1v.w);
    float4* op = (float4*)(out + (size_t)d * 256 + lane * 8);
    op[0] = o0; op[1] = o1;
}

// ---------------------------------------------------------------------------
// Layer-2 GAT gather + final epilogue (bias, elu, output write, score head).
// ---------------------------------------------------------------------------
__global__ __launch_bounds__(256) void gather2_kernel(
    const int* __restrict__ rp, const int* __restrict__ col,
    const float* __restrict__ h2,
    const float* __restrict__ asrc, const float* __restrict__ adst,
    const float* __restrict__ b2, const float* __restrict__ Ws,
    const float* __restrict__ bs, float* __restrict__ out, int N)
{
    __shared__ float s_w[8][WCAP];
    int warp = threadIdx.x >> 5, lane = threadIdx.x & 31;
    int d = blockIdx.x * 8 + warp;
    if (d >= N) return;

    int beg = rp[d];
    int deg = rp[d + 1] - beg;
    float adv = __ldg(adst + d);

    float pden = 0.f;
    for (int e = lane; e < deg; e += 32) {
        int s = __ldg(col + beg + e);
        float w = __expf(lrelu(__ldg(asrc + s) + adv));
        if (e < WCAP) s_w[warp][e] = w;
        pden += w;
    }
#pragma unroll
    for (int off = 16; off; off >>= 1) pden += __shfl_xor_sync(0xffffffffu, pden, off);
    float w_self = __expf(lrelu(__ldg(asrc + d) + adv));
    float inv_den = 1.f / (pden + w_self + 1e-16f);
    __syncwarp();

    float2 acc;
    {
        float2 v = __ldg((const float2*)(h2 + (size_t)d * 64) + lane);
        float a = w_self * inv_den;
        acc.x = a * v.x; acc.y = a * v.y;
    }
    for (int e = 0; e < deg; e++) {
        int s = __ldg(col + beg + e);
        float w = (e < WCAP) ? s_w[warp][e]
                             : __expf(lrelu(__ldg(asrc + s) + adv));
        float alpha = w * inv_den;
        float2 v = __ldg((const float2*)(h2 + (size_t)s * 64) + lane);
        acc.x += alpha * v.x; acc.y += alpha * v.y;
    }
    float o0 = elu(acc.x + __ldg(b2 + lane * 2));
    float o1 = elu(acc.y + __ldg(b2 + lane * 2 + 1));
    *(float2*)(out + (size_t)d * 64 + lane * 2) = make_float2(o0, o1);
    float sc = o0 * __ldg(Ws + lane * 2) + o1 * __ldg(Ws + lane * 2 + 1);
#pragma unroll
    for (int off = 16; off; off >>= 1) sc += __shfl_xor_sync(0xffffffffu, sc, off);
    if (lane == 0) out[(size_t)N * 64 + d] = sc + __ldg(bs);
}

// ---------------------------------------------------------------------------
// Launch
// ---------------------------------------------------------------------------
extern "C" void kernel_launch(void* const* d_in, const int* in_sizes, int n_in,
                              void* d_out, int out_size)
{
    const float* x   = (const float*)d_in[0];
    const int*   ei  = (const int*)d_in[1];
    const float* W1  = (const float*)d_in[2];
    const float* as1 = (const float*)d_in[3];
    const float* ad1 = (const float*)d_in[4];
    const float* b1  = (const float*)d_in[5];
    const float* W2  = (const float*)d_in[6];
    const float* as2 = (const float*)d_in[7];
    const float* ad2 = (const float*)d_in[8];
    const float* b2  = (const float*)d_in[9];
    const float* Ws  = (const float*)d_in[10];
    const float* bs  = (const float*)d_in[11];
    float*       out = (float*)d_out;

    const int N = in_sizes[0] / 128;
    const int E = in_sizes[1] / 2;

    float *h1, *hm, *h2, *as1p, *ad1p, *as2p, *ad2p;
    int *cnt, *rp, *cur, *colp;
    cudaGetSymbolAddress((void**)&h1,   g_h1);
    cudaGetSymbolAddress((void**)&hm,   g_hm);
    cudaGetSymbolAddress((void**)&h2,   g_h2);
    cudaGetSymbolAddress((void**)&as1p, g_as1);
    cudaGetSymbolAddress((void**)&ad1p, g_ad1);
    cudaGetSymbolAddress((void**)&as2p, g_as2);
    cudaGetSymbolAddress((void**)&ad2p, g_ad2);
    cudaGetSymbolAddress((void**)&cnt,  g_cnt);
    cudaGetSymbolAddress((void**)&rp,   g_rp);
    cudaGetSymbolAddress((void**)&cur,  g_cur);
    cudaGetSymbolAddress((void**)&colp, g_col);

    // CSR build (by dst)
    zero_cnt<<<(N + 255) / 256, 256>>>(cnt, N);
    count_kernel<<<(E + 255) / 256, 256>>>(ei, cnt, E);
    scan_kernel<<<1, 1024>>>(cnt, rp, cur, N);
    fill_kernel<<<(E + 255) / 256, 256>>>(ei, cur, colp, E);

    // Layer 1
    sgemm_kernel<128, 128, 16, 8, 8>
        <<<dim3(2, (N + 127) / 128), 256>>>(N, 256, 128, x, W1, h1);
    att1_kernel<<<(N * 32 + 255) / 256, 256>>>(h1, as1, ad1, as1p, ad1p, N);
    gather1_kernel<<<(N + 7) / 8, 256>>>(rp, colp, h1, as1p, ad1p, b1, hm, N);

    // Layer 2
    sgemm_kernel<128, 64, 16, 8, 4>
        <<<dim3(1, (N + 127) / 128), 256>>>(N, 64, 256, hm, W2, h2);
    att2_kernel<<<(N * 32 + 255) / 256, 256>>>(h2, as2, ad2, as2p, ad2p, N);
    gather2_kernel<<<(N + 7) / 8, 256>>>(rp, colp, h2, as2p, ad2p, b2, Ws, bs, out, N);
}

// round 6
// speedup vs baseline: 1.9024x; 1.2696x over previous
#include <cuda_runtime.h>
#include <cstdint>

// ---------------------------------------------------------------------------
// Fixed dataset: N=50000, E=800000, IN=128, L1: 4 heads x 64, L2: 1 head x 64.
// edge_index is int32: ei[0:E]=src, ei[E:2E]=dst. Self-loops handled in-warp.
// ---------------------------------------------------------------------------
#define NMAX 50000
#define EMAX 810000

__device__ __align__(16) float g_h1 [NMAX * 256];  // layer1 linear output
__device__ __align__(16) float g_hm [NMAX * 256];  // layer1 GAT output (elu'd) = layer2 input
__device__ __align__(16) float g_h2 [NMAX * 64];   // layer2 linear output
__device__ __align__(16) float g_as1[NMAX * 4];
__device__ __align__(16) float g_ad1[NMAX * 4];
__device__ __align__(16) float g_as2[NMAX];
__device__ __align__(16) float g_ad2[NMAX];
// CSR by dst
__device__ int g_cnt [NMAX];
__device__ int g_rp  [NMAX + 1];
__device__ int g_cur [NMAX];
__device__ int g_col [EMAX];

__device__ __forceinline__ float lrelu(float x) { return x > 0.f ? x : 0.2f * x; }
__device__ __forceinline__ float elu(float x)   { return x > 0.f ? x : expm1f(x); }
// tf32 is a b32 storage type in PTX: destination must be a b32 ("r") register.
__device__ __forceinline__ uint32_t to_tf32(float x) {
    uint32_t r;
    asm("cvt.rna.tf32.f32 %0, %1;" : "=r"(r) : "f"(x));
    return r;
}

// ---------------------------------------------------------------------------
// CSR build
// ---------------------------------------------------------------------------
__global__ void count_kernel(const int* __restrict__ ei, int* cnt, int E) {
    int e = blockIdx.x * blockDim.x + threadIdx.x;
    if (e < E) atomicAdd(cnt + ei[E + e], 1);
}

// Single-block exclusive scan (N <= 1024*64)
__global__ void scan_kernel(const int* __restrict__ cnt, int* rp, int* cur, int N) {
    __shared__ int sums[1024];
    int t = threadIdx.x;
    int C = (N + 1023) / 1024;
    int b0 = t * C, b1 = min(N, b0 + C);
    int s = 0;
    for (int i = b0; i < b1; i++) s += cnt[i];
    sums[t] = s;
    __syncthreads();
    for (int off = 1; off < 1024; off <<= 1) {
        int v = (t >= off) ? sums[t - off] : 0;
        __syncthreads();
        sums[t] += v;
        __syncthreads();
    }
    int run = (t == 0) ? 0 : sums[t - 1];
    for (int i = b0; i < b1; i++) { rp[i] = run; cur[i] = run; run += cnt[i]; }
    if (b0 < N && b1 == N) rp[N] = run;
}

__global__ void fill_kernel(const int* __restrict__ ei, int* cur, int* col, int E) {
    int e = blockIdx.x * blockDim.x + threadIdx.x;
    if (e >= E) return;
    int d = ei[E + e];
    int pos = atomicAdd(cur + d, 1);
    col[pos] = ei[e];
}

// ---------------------------------------------------------------------------
// TF32 tensor-core GEMM: C[M,Nc] = A[M,K] @ B[K,Nc], row-major fp32 in/out.
// Block tile 128x64, BK=32. 256 threads = 8 warps; warp tile 32x32 via
// mma.sync.m16n8k8 (2 m-frags x 4 n-frags). Requires K%32==0, Nc%64==0.
// Padded smem strides chosen so fragment loads are bank-conflict-free.
// ---------------------------------------------------------------------------
#define AKP 36   // A smem row stride: bank = (r*36+c)%32 = (4r+c)%32, unique
#define BNP 72   // B smem row stride: bank = (k*72+n)%32 = (8k+n)%32, unique

__global__ __launch_bounds__(256) void tf32_gemm(
    int M, int Nc, int K,
    const float* __restrict__ A, const float* __restrict__ B, float* __restrict__ C)
{
    __shared__ uint32_t As[128][AKP];
    __shared__ uint32_t Bs[32][BNP];

    const int tid    = threadIdx.x;
    const int lane   = tid & 31;
    const int wid    = tid >> 5;
    const int warp_m = wid & 3;        // 4 m-bands of 32
    const int warp_n = wid >> 2;       // 2 n-bands of 32
    const int bn0    = blockIdx.x * 64;
    const int bm0    = blockIdx.y * 128;

    float acc[2][4][4];
#pragma unroll
    for (int i = 0; i < 2; i++)
#pragma unroll
        for (int j = 0; j < 4; j++)
#pragma unroll
            for (int k = 0; k < 4; k++) acc[i][j][k] = 0.f;

    const int rA = lane >> 2;          // fragment row 0..7
    const int cA = lane & 3;           // fragment col 0..3

    for (int k0 = 0; k0 < K; k0 += 32) {
        // Load A tile 128x32 (4 float4 per thread), convert to tf32
#pragma unroll
        for (int t = 0; t < 4; t++) {
            int i = tid + t * 256;         // 0..1023
            int r = i >> 3;                // /8
            int c = (i & 7) * 4;
            int gr = bm0 + r;
            float4 v = (gr < M) ? *(const float4*)(A + (size_t)gr * K + k0 + c)
                                : make_float4(0.f, 0.f, 0.f, 0.f);
            uint4 u = make_uint4(to_tf32(v.x), to_tf32(v.y), to_tf32(v.z), to_tf32(v.w));
            *(uint4*)&As[r][c] = u;
        }
        // Load B tile 32x64 (2 float4 per thread), convert to tf32
#pragma unroll
        for (int t = 0; t < 2; t++) {
            int i = tid + t * 256;         // 0..511
            int r = i >> 4;                // /16
            int c = (i & 15) * 4;
            float4 v = *(const float4*)(B + (size_t)(k0 + r) * Nc + bn0 + c);
            uint4 u = make_uint4(to_tf32(v.x), to_tf32(v.y), to_tf32(v.z), to_tf32(v.w));
            *(uint4*)&Bs[r][c] = u;
        }
        __syncthreads();

#pragma unroll
        for (int kk = 0; kk < 32; kk += 8) {
            uint32_t a[2][4];
#pragma unroll
            for (int mf = 0; mf < 2; mf++) {
                int r0 = warp_m * 32 + mf * 16 + rA;
                a[mf][0] = As[r0    ][kk + cA];
                a[mf][1] = As[r0 + 8][kk + cA];
                a[mf][2] = As[r0    ][kk + cA + 4];
                a[mf][3] = As[r0 + 8][kk + cA + 4];
            }
            uint32_t b[4][2];
#pragma unroll
            for (int nf = 0; nf < 4; nf++) {
                int n0 = warp_n * 32 + nf * 8 + rA;
                b[nf][0] = Bs[kk + cA    ][n0];
                b[nf][1] = Bs[kk + cA + 4][n0];
            }
#pragma unroll
            for (int mf = 0; mf < 2; mf++)
#pragma unroll
                for (int nf = 0; nf < 4; nf++) {
                    asm volatile(
                        "mma.sync.aligned.m16n8k8.row.col.f32.tf32.tf32.f32 "
                        "{%0,%1,%2,%3}, {%4,%5,%6,%7}, {%8,%9}, {%0,%1,%2,%3};"
                        : "+f"(acc[mf][nf][0]), "+f"(acc[mf][nf][1]),
                          "+f"(acc[mf][nf][2]), "+f"(acc[mf][nf][3])
                        : "r"(a[mf][0]), "r"(a[mf][1]), "r"(a[mf][2]), "r"(a[mf][3]),
                          "r"(b[nf][0]), "r"(b[nf][1]));
                }
        }
        __syncthreads();
    }

    // Store: c0,c1 at (row, 2c),(row,2c+1); c2,c3 at (row+8, ...)
#pragma unroll
    for (int mf = 0; mf < 2; mf++) {
        int r0 = bm0 + warp_m * 32 + mf * 16 + rA;
#pragma unroll
        for (int nf = 0; nf < 4; nf++) {
            int cc = bn0 + warp_n * 32 + nf * 8 + cA * 2;
            if (r0 < M)
                *(float2*)(C + (size_t)r0 * Nc + cc)
                    = make_float2(acc[mf][nf][0], acc[mf][nf][1]);
            if (r0 + 8 < M)
                *(float2*)(C + (size_t)(r0 + 8) * Nc + cc)
                    = make_float2(acc[mf][nf][2], acc[mf][nf][3]);
        }
    }
}

// ---------------------------------------------------------------------------
// Attention scalar kernels
// ---------------------------------------------------------------------------
__global__ void att1_kernel(const float* __restrict__ h1,
                            const float* __restrict__ att_s,
                            const float* __restrict__ att_d,
                            float* __restrict__ asrc, float* __restrict__ adst, int N)
{
    int w    = (blockIdx.x * blockDim.x + threadIdx.x) >> 5;
    int lane = threadIdx.x & 31;
    if (w >= N) return;
    const float* row = h1 + (size_t)w * 256;
    float s[4] = {0.f,0.f,0.f,0.f}, d[4] = {0.f,0.f,0.f,0.f};
#pragma unroll
    for (int k = 0; k < 8; k++) {
        int idx = lane + k * 32;
        float v = row[idx];
        s[k >> 1] += v * att_s[idx];
        d[k >> 1] += v * att_d[idx];
    }
#pragma unroll
    for (int h = 0; h < 4; h++) {
        float a = s[h], b = d[h];
#pragma unroll
        for (int off = 16; off; off >>= 1) {
            a += __shfl_xor_sync(0xffffffffu, a, off);
            b += __shfl_xor_sync(0xffffffffu, b, off);
        }
        if (lane == 0) { asrc[w * 4 + h] = a; adst[w * 4 + h] = b; }
    }
}

__global__ void att2_kernel(const float* __restrict__ h2,
                            const float* __restrict__ att_s,
                            const float* __restrict__ att_d,
                            float* __restrict__ asrc, float* __restrict__ adst, int N)
{
    int w    = (blockIdx.x * blockDim.x + threadIdx.x) >> 5;
    int lane = threadIdx.x & 31;
    if (w >= N) return;
    const float* row = h2 + (size_t)w * 64;
    float v0 = row[lane], v1 = row[lane + 32];
    float a = v0 * att_s[lane] + v1 * att_s[lane + 32];
    float b = v0 * att_d[lane] + v1 * att_d[lane + 32];
#pragma unroll
    for (int off = 16; off; off >>= 1) {
        a += __shfl_xor_sync(0xffffffffu, a, off);
        b += __shfl_xor_sync(0xffffffffu, b, off);
    }
    if (lane == 0) { asrc[w] = a; adst[w] = b; }
}

// ---------------------------------------------------------------------------
// Layer-1 GAT gather: one warp per dst node. No atomics.
// ---------------------------------------------------------------------------
#define WCAP 128

__global__ __launch_bounds__(256) void gather1_kernel(
    const int* __restrict__ rp, const int* __restrict__ col,
    const float* __restrict__ h1,
    const float* __restrict__ asrc, const float* __restrict__ adst,
    const float* __restrict__ bias, float* __restrict__ out, int N)
{
    __shared__ float s_w[8][WCAP * 4];
    int warp = threadIdx.x >> 5, lane = threadIdx.x & 31;
    int d = blockIdx.x * 8 + warp;
    if (d >= N) return;

    int beg = rp[d];
    int deg = rp[d + 1] - beg;
    int hme = lane & 3;
    float ad_hme = __ldg(adst + (size_t)d * 4 + hme);

    float pden = 0.f;
    int npairs = deg * 4;
    for (int idx = lane; idx < npairs; idx += 32) {
        int e = idx >> 2;
        int s = __ldg(col + beg + e);
        float w = __expf(lrelu(__ldg(asrc + (size_t)s * 4 + hme) + ad_hme));
        if (e < WCAP) s_w[warp][idx] = w;
        pden += w;
    }
    pden += __shfl_xor_sync(0xffffffffu, pden, 4);
    pden += __shfl_xor_sync(0xffffffffu, pden, 8);
    pden += __shfl_xor_sync(0xffffffffu, pden, 16);
    float w_self = __expf(lrelu(__ldg(asrc + (size_t)d * 4 + hme) + ad_hme));
    float inv_den = 1.f / (pden + w_self + 1e-16f);
    __syncwarp();

    int head = lane >> 3;
    float inv_h   = __shfl_sync(0xffffffffu, inv_den, head);
    float aself_h = __shfl_sync(0xffffffffu, w_self,  head) * inv_h;
    float ad_head = __shfl_sync(0xffffffffu, ad_hme,  head);

    float acc[8];
    {
        const float4* hp = (const float4*)(h1 + (size_t)d * 256 + lane * 8);
        float4 v0 = __ldg(hp), v1 = __ldg(hp + 1);
        acc[0]=aself_h*v0.x; acc[1]=aself_h*v0.y; acc[2]=aself_h*v0.z; acc[3]=aself_h*v0.w;
        acc[4]=aself_h*v1.x; acc[5]=aself_h*v1.y; acc[6]=aself_h*v1.z; acc[7]=aself_h*v1.w;
    }
    for (int e = 0; e < deg; e++) {
        int s = __ldg(col + beg + e);
        float w = (e < WCAP) ? s_w[warp][e * 4 + head]
                             : __expf(lrelu(__ldg(asrc + (size_t)s * 4 + head) + ad_head));
        float alpha = w * inv_h;
        const float4* hp = (const float4*)(h1 + (size_t)s * 256 + lane * 8);
        float4 v0 = __ldg(hp), v1 = __ldg(hp + 1);
        acc[0]+=alpha*v0.x; acc[1]+=alpha*v0.y; acc[2]+=alpha*v0.z; acc[3]+=alpha*v0.w;
        acc[4]+=alpha*v1.x; acc[5]+=alpha*v1.y; acc[6]+=alpha*v1.z; acc[7]+=alpha*v1.w;
    }
    const float4* bp = (const float4*)(bias + lane * 8);
    float4 b0 = __ldg(bp), b1v = __ldg(bp + 1);
    float4 o0, o1;
    o0.x=elu(acc[0]+b0.x);  o0.y=elu(acc[1]+b0.y);  o0.z=elu(acc[2]+b0.z);  o0.w=elu(acc[3]+b0.w);
    o1.x=elu(acc[4]+b1v.x); o1.y=elu(acc[5]+b1v.y); o1.z=elu(acc[6]+b1v.z); o1.w=elu(acc[7]+b1v.w);
    float4* op = (float4*)(out + (size_t)d * 256 + lane * 8);
    op[0] = o0; op[1] = o1;
}

// ---------------------------------------------------------------------------
// Layer-2 GAT gather + final epilogue.
// ---------------------------------------------------------------------------
__global__ __launch_bounds__(256) void gather2_kernel(
    const int* __restrict__ rp, const int* __restrict__ col,
    const float* __restrict__ h2,
    const float* __restrict__ asrc, const float* __restrict__ adst,
    const float* __restrict__ b2, const float* __restrict__ Ws,
    const float* __restrict__ bs, float* __restrict__ out, int N)
{
    __shared__ float s_w[8][WCAP];
    int warp = threadIdx.x >> 5, lane = threadIdx.x & 31;
    int d = blockIdx.x * 8 + warp;
    if (d >= N) return;

    int beg = rp[d];
    int deg = rp[d + 1] - beg;
    float adv = __ldg(adst + d);

    float pden = 0.f;
    for (int e = lane; e < deg; e += 32) {
        int s = __ldg(col + beg + e);
        float w = __expf(lrelu(__ldg(asrc + s) + adv));
        if (e < WCAP) s_w[warp][e] = w;
        pden += w;
    }
#pragma unroll
    for (int off = 16; off; off >>= 1) pden += __shfl_xor_sync(0xffffffffu, pden, off);
    float w_self = __expf(lrelu(__ldg(asrc + d) + adv));
    float inv_den = 1.f / (pden + w_self + 1e-16f);
    __syncwarp();

    float2 acc;
    {
        float2 v = __ldg((const float2*)(h2 + (size_t)d * 64) + lane);
        float a = w_self * inv_den;
        acc.x = a * v.x; acc.y = a * v.y;
    }
    for (int e = 0; e < deg; e++) {
        int s = __ldg(col + beg + e);
        float w = (e < WCAP) ? s_w[warp][e]
                             : __expf(lrelu(__ldg(asrc + s) + adv));
        float alpha = w * inv_den;
        float2 v = __ldg((const float2*)(h2 + (size_t)s * 64) + lane);
        acc.x += alpha * v.x; acc.y += alpha * v.y;
    }
    float o0 = elu(acc.x + __ldg(b2 + lane * 2));
    float o1 = elu(acc.y + __ldg(b2 + lane * 2 + 1));
    *(float2*)(out + (size_t)d * 64 + lane * 2) = make_float2(o0, o1);
    float sc = o0 * __ldg(Ws + lane * 2) + o1 * __ldg(Ws + lane * 2 + 1);
#pragma unroll
    for (int off = 16; off; off >>= 1) sc += __shfl_xor_sync(0xffffffffu, sc, off);
    if (lane == 0) out[(size_t)N * 64 + d] = sc + __ldg(bs);
}

// ---------------------------------------------------------------------------
// Launch
// ---------------------------------------------------------------------------
extern "C" void kernel_launch(void* const* d_in, const int* in_sizes, int n_in,
                              void* d_out, int out_size)
{
    const float* x   = (const float*)d_in[0];
    const int*   ei  = (const int*)d_in[1];
    const float* W1  = (const float*)d_in[2];
    const float* as1 = (const float*)d_in[3];
    const float* ad1 = (const float*)d_in[4];
    const float* b1  = (const float*)d_in[5];
    const float* W2  = (const float*)d_in[6];
    const float* as2 = (const float*)d_in[7];
    const float* ad2 = (const float*)d_in[8];
    const float* b2  = (const float*)d_in[9];
    const float* Ws  = (const float*)d_in[10];
    const float* bs  = (const float*)d_in[11];
    float*       out = (float*)d_out;

    const int N = in_sizes[0] / 128;
    const int E = in_sizes[1] / 2;

    float *h1, *hm, *h2, *as1p, *ad1p, *as2p, *ad2p;
    int *cnt, *rp, *cur, *colp;
    cudaGetSymbolAddress((void**)&h1,   g_h1);
    cudaGetSymbolAddress((void**)&hm,   g_hm);
    cudaGetSymbolAddress((void**)&h2,   g_h2);
    cudaGetSymbolAddress((void**)&as1p, g_as1);
    cudaGetSymbolAddress((void**)&ad1p, g_ad1);
    cudaGetSymbolAddress((void**)&as2p, g_as2);
    cudaGetSymbolAddress((void**)&ad2p, g_ad2);
    cudaGetSymbolAddress((void**)&cnt,  g_cnt);
    cudaGetSymbolAddress((void**)&rp,   g_rp);
    cudaGetSymbolAddress((void**)&cur,  g_cur);
    cudaGetSymbolAddress((void**)&colp, g_col);

    // CSR build (by dst)
    cudaMemsetAsync(cnt, 0, (size_t)N * sizeof(int));
    count_kernel<<<(E + 255) / 256, 256>>>(ei, cnt, E);
    scan_kernel<<<1, 1024>>>(cnt, rp, cur, N);
    fill_kernel<<<(E + 255) / 256, 256>>>(ei, cur, colp, E);

    // Layer 1
    tf32_gemm<<<dim3(4, (N + 127) / 128), 256>>>(N, 256, 128, x, W1, h1);
    att1_kernel<<<(N * 32 + 255) / 256, 256>>>(h1, as1, ad1, as1p, ad1p, N);
    gather1_kernel<<<(N + 7) / 8, 256>>>(rp, colp, h1, as1p, ad1p, b1, hm, N);

    // Layer 2
    tf32_gemm<<<dim3(1, (N + 127) / 128), 256>>>(N, 64, 256, hm, W2, h2);
    att2_kernel<<<(N * 32 + 255) / 256, 256>>>(h2, as2, ad2, as2p, ad2p, N);
    gather2_kernel<<<(N + 7) / 8, 256>>>(rp, colp, h2, as2p, ad2p, b2, Ws, bs, out, N);
}

// round 7
// speedup vs baseline: 2.0048x; 1.0538x over previous
#include <cuda_runtime.h>
#include <cstdint>

// ---------------------------------------------------------------------------
// Fixed dataset: N=50000, E=800000, IN=128, L1: 4 heads x 64, L2: 1 head x 64.
// edge_index is int32: ei[0:E]=src, ei[E:2E]=dst. Self-loops handled in-warp.
// ---------------------------------------------------------------------------
#define NMAX 50000
#define EMAX 810000

__device__ __align__(16) float g_h1 [NMAX * 256];  // layer1 linear output
__device__ __align__(16) float g_hm [NMAX * 256];  // layer1 GAT output (elu'd)
__device__ __align__(16) float g_h2 [NMAX * 64];   // layer2 linear output
__device__ __align__(16) float g_as1[NMAX * 4];
__device__ __align__(16) float g_ad1[NMAX * 4];
__device__ __align__(16) float g_as2[NMAX];
__device__ __align__(16) float g_ad2[NMAX];
// CSR by dst
__device__ int g_cnt [NMAX];
__device__ int g_rp  [NMAX + 1];
__device__ int g_cur [NMAX];
__device__ int g_col [EMAX];

__device__ __forceinline__ float lrelu(float x) { return x > 0.f ? x : 0.2f * x; }
__device__ __forceinline__ float elu(float x)   { return x > 0.f ? x : expm1f(x); }
__device__ __forceinline__ uint32_t to_tf32(float x) {
    uint32_t r;
    asm("cvt.rna.tf32.f32 %0, %1;" : "=r"(r) : "f"(x));
    return r;
}

// ---------------------------------------------------------------------------
// CSR build
// ---------------------------------------------------------------------------
__global__ void count_kernel(const int* __restrict__ ei, int* cnt, int E) {
    int e = blockIdx.x * blockDim.x + threadIdx.x;
    if (e < E) atomicAdd(cnt + ei[E + e], 1);
}

__global__ void scan_kernel(const int* __restrict__ cnt, int* rp, int* cur, int N) {
    __shared__ int sums[1024];
    int t = threadIdx.x;
    int C = (N + 1023) / 1024;
    int b0 = t * C, b1 = min(N, b0 + C);
    int s = 0;
    for (int i = b0; i < b1; i++) s += cnt[i];
    sums[t] = s;
    __syncthreads();
    for (int off = 1; off < 1024; off <<= 1) {
        int v = (t >= off) ? sums[t - off] : 0;
        __syncthreads();
        sums[t] += v;
        __syncthreads();
    }
    int run = (t == 0) ? 0 : sums[t - 1];
    for (int i = b0; i < b1; i++) { rp[i] = run; cur[i] = run; run += cnt[i]; }
    if (b0 < N && b1 == N) rp[N] = run;
}

__global__ void fill_kernel(const int* __restrict__ ei, int* cur, int* col, int E) {
    int e = blockIdx.x * blockDim.x + threadIdx.x;
    if (e >= E) return;
    int d = ei[E + e];
    int pos = atomicAdd(cur + d, 1);
    col[pos] = ei[e];
}

// ---------------------------------------------------------------------------
// TF32 tensor-core GEMM with register prefetch + fused attention-scalar
// epilogue. C[M,Nc] = A[M,K] @ B[K,Nc]. Block tile 128x64, BK=32, 8 warps,
// warp tile 32x32 via mma.m16n8k8. Block column bn == head bn (64 channels),
// so a_src/a_dst for that head reduce entirely within the block.
// ---------------------------------------------------------------------------
#define AKP 36
#define BNP 72

__global__ __launch_bounds__(256) void tf32_gemm(
    int M, int Nc, int K,
    const float* __restrict__ A, const float* __restrict__ B, float* __restrict__ C,
    const float* __restrict__ att_s, const float* __restrict__ att_d,
    float* __restrict__ asrc, float* __restrict__ adst, int astride)
{
    __shared__ uint32_t As[128][AKP];
    __shared__ uint32_t Bs[32][BNP];
    __shared__ float s_ps[2][128];
    __shared__ float s_pd[2][128];

    const int tid    = threadIdx.x;
    const int lane   = tid & 31;
    const int wid    = tid >> 5;
    const int warp_m = wid & 3;
    const int warp_n = wid >> 2;
    const int bn0    = blockIdx.x * 64;
    const int bm0    = blockIdx.y * 128;

    float acc[2][4][4];
#pragma unroll
    for (int i = 0; i < 2; i++)
#pragma unroll
        for (int j = 0; j < 4; j++)
#pragma unroll
            for (int k = 0; k < 4; k++) acc[i][j][k] = 0.f;

    const int rA = lane >> 2;
    const int cA = lane & 3;

    float4 pa[4], pb[2];
    // initial tile loads (k0 = 0)
#pragma unroll
    for (int t = 0; t < 4; t++) {
        int i = tid + t * 256, r = i >> 3, c = (i & 7) * 4;
        int gr = bm0 + r;
        pa[t] = (gr < M) ? *(const float4*)(A + (size_t)gr * K + c)
                         : make_float4(0.f, 0.f, 0.f, 0.f);
    }
#pragma unroll
    for (int t = 0; t < 2; t++) {
        int i = tid + t * 256, r = i >> 4, c = (i & 15) * 4;
        pb[t] = *(const float4*)(B + (size_t)r * Nc + bn0 + c);
    }

    for (int k0 = 0; k0 < K; k0 += 32) {
        // convert + store current tile
#pragma unroll
        for (int t = 0; t < 4; t++) {
            int i = tid + t * 256, r = i >> 3, c = (i & 7) * 4;
            uint4 u = make_uint4(to_tf32(pa[t].x), to_tf32(pa[t].y),
                                 to_tf32(pa[t].z), to_tf32(pa[t].w));
            *(uint4*)&As[r][c] = u;
        }
#pragma unroll
        for (int t = 0; t < 2; t++) {
            int i = tid + t * 256, r = i >> 4, c = (i & 15) * 4;
            uint4 u = make_uint4(to_tf32(pb[t].x), to_tf32(pb[t].y),
                                 to_tf32(pb[t].z), to_tf32(pb[t].w));
            *(uint4*)&Bs[r][c] = u;
        }
        __syncthreads();

        // prefetch next tile while tensor cores run
        int kn = k0 + 32;
        if (kn < K) {
#pragma unroll
            for (int t = 0; t < 4; t++) {
                int i = tid + t * 256, r = i >> 3, c = (i & 7) * 4;
                int gr = bm0 + r;
                pa[t] = (gr < M) ? *(const float4*)(A + (size_t)gr * K + kn + c)
                                 : make_float4(0.f, 0.f, 0.f, 0.f);
            }
#pragma unroll
            for (int t = 0; t < 2; t++) {
                int i = tid + t * 256, r = i >> 4, c = (i & 15) * 4;
                pb[t] = *(const float4*)(B + (size_t)(kn + r) * Nc + bn0 + c);
            }
        }

#pragma unroll
        for (int kk = 0; kk < 32; kk += 8) {
            uint32_t a[2][4];
#pragma unroll
            for (int mf = 0; mf < 2; mf++) {
                int r0 = warp_m * 32 + mf * 16 + rA;
                a[mf][0] = As[r0    ][kk + cA];
                a[mf][1] = As[r0 + 8][kk + cA];
                a[mf][2] = As[r0    ][kk + cA + 4];
                a[mf][3] = As[r0 + 8][kk + cA + 4];
            }
            uint32_t b[4][2];
#pragma unroll
            for (int nf = 0; nf < 4; nf++) {
                int n0 = warp_n * 32 + nf * 8 + rA;
                b[nf][0] = Bs[kk + cA    ][n0];
                b[nf][1] = Bs[kk + cA + 4][n0];
            }
#pragma unroll
            for (int mf = 0; mf < 2; mf++)
#pragma unroll
                for (int nf = 0; nf < 4; nf++) {
                    asm volatile(
                        "mma.sync.aligned.m16n8k8.row.col.f32.tf32.tf32.f32 "
                        "{%0,%1,%2,%3}, {%4,%5,%6,%7}, {%8,%9}, {%0,%1,%2,%3};"
                        : "+f"(acc[mf][nf][0]), "+f"(acc[mf][nf][1]),
                          "+f"(acc[mf][nf][2]), "+f"(acc[mf][nf][3])
                        : "r"(a[mf][0]), "r"(a[mf][1]), "r"(a[mf][2]), "r"(a[mf][3]),
                          "r"(b[nf][0]), "r"(b[nf][1]));
                }
        }
        __syncthreads();
    }

    // Store C
#pragma unroll
    for (int mf = 0; mf < 2; mf++) {
        int r0 = bm0 + warp_m * 32 + mf * 16 + rA;
#pragma unroll
        for (int nf = 0; nf < 4; nf++) {
            int cc = bn0 + warp_n * 32 + nf * 8 + cA * 2;
            if (r0 < M)
                *(float2*)(C + (size_t)r0 * Nc + cc)
                    = make_float2(acc[mf][nf][0], acc[mf][nf][1]);
            if (r0 + 8 < M)
                *(float2*)(C + (size_t)(r0 + 8) * Nc + cc)
                    = make_float2(acc[mf][nf][2], acc[mf][nf][3]);
        }
    }

    // Fused attention scalars: a_src/a_dst for head blockIdx.x over this
    // block's 128 rows (attention uses h WITHOUT bias -> acc is exactly h).
    const int hb = blockIdx.x * 64;
    float ps[2][2] = {{0.f,0.f},{0.f,0.f}}, pd[2][2] = {{0.f,0.f},{0.f,0.f}};
#pragma unroll
    for (int mf = 0; mf < 2; mf++)
#pragma unroll
        for (int nf = 0; nf < 4; nf++) {
            int cloc = warp_n * 32 + nf * 8 + cA * 2;
            float a_s0 = __ldg(att_s + hb + cloc), a_s1 = __ldg(att_s + hb + cloc + 1);
            float a_d0 = __ldg(att_d + hb + cloc), a_d1 = __ldg(att_d + hb + cloc + 1);
            ps[mf][0] += acc[mf][nf][0] * a_s0 + acc[mf][nf][1] * a_s1;
            ps[mf][1] += acc[mf][nf][2] * a_s0 + acc[mf][nf][3] * a_s1;
            pd[mf][0] += acc[mf][nf][0] * a_d0 + acc[mf][nf][1] * a_d1;
            pd[mf][1] += acc[mf][nf][2] * a_d0 + acc[mf][nf][3] * a_d1;
        }
    // reduce over the 4 lanes (cA) sharing each row
#pragma unroll
    for (int mf = 0; mf < 2; mf++)
#pragma unroll
        for (int hh = 0; hh < 2; hh++) {
            ps[mf][hh] += __shfl_xor_sync(0xffffffffu, ps[mf][hh], 1);
            ps[mf][hh] += __shfl_xor_sync(0xffffffffu, ps[mf][hh], 2);
            pd[mf][hh] += __shfl_xor_sync(0xffffffffu, pd[mf][hh], 1);
            pd[mf][hh] += __shfl_xor_sync(0xffffffffu, pd[mf][hh], 2);
        }
    if (cA == 0) {
#pragma unroll
        for (int mf = 0; mf < 2; mf++) {
            int r0 = warp_m * 32 + mf * 16 + rA;
            s_ps[warp_n][r0]     = ps[mf][0];
            s_ps[warp_n][r0 + 8] = ps[mf][1];
            s_pd[warp_n][r0]     = pd[mf][0];
            s_pd[warp_n][r0 + 8] = pd[mf][1];
        }
    }
    __syncthreads();
    if (tid < 128) {
        int gr = bm0 + tid;
        if (gr < M) {
            asrc[(size_t)gr * astride + blockIdx.x] = s_ps[0][tid] + s_ps[1][tid];
            adst[(size_t)gr * astride + blockIdx.x] = s_pd[0][tid] + s_pd[1][tid];
        }
    }
}

// ---------------------------------------------------------------------------
// Layer-1 GAT gather: one warp per dst node. No atomics.
// ---------------------------------------------------------------------------
#define WCAP 128

__global__ __launch_bounds__(256) void gather1_kernel(
    const int* __restrict__ rp, const int* __restrict__ col,
    const float* __restrict__ h1,
    const float* __restrict__ asrc, const float* __restrict__ adst,
    const float* __restrict__ bias, float* __restrict__ out, int N)
{
    __shared__ float s_w[8][WCAP * 4];
    int warp = threadIdx.x >> 5, lane = threadIdx.x & 31;
    int d = blockIdx.x * 8 + warp;
    if (d >= N) return;

    int beg = rp[d];
    int deg = rp[d + 1] - beg;
    int hme = lane & 3;
    float ad_hme = __ldg(adst + (size_t)d * 4 + hme);

    float pden = 0.f;
    int npairs = deg * 4;
    for (int idx = lane; idx < npairs; idx += 32) {
        int e = idx >> 2;
        int s = __ldg(col + beg + e);
        float w = __expf(lrelu(__ldg(asrc + (size_t)s * 4 + hme) + ad_hme));
        if (e < WCAP) s_w[warp][idx] = w;
        pden += w;
    }
    pden += __shfl_xor_sync(0xffffffffu, pden, 4);
    pden += __shfl_xor_sync(0xffffffffu, pden, 8);
    pden += __shfl_xor_sync(0xffffffffu, pden, 16);
    float w_self = __expf(lrelu(__ldg(asrc + (size_t)d * 4 + hme) + ad_hme));
    float inv_den = 1.f / (pden + w_self + 1e-16f);
    __syncwarp();

    int head = lane >> 3;
    float inv_h   = __shfl_sync(0xffffffffu, inv_den, head);
    float aself_h = __shfl_sync(0xffffffffu, w_self,  head) * inv_h;
    float ad_head = __shfl_sync(0xffffffffu, ad_hme,  head);

    float acc[8];
    {
        const float4* hp = (const float4*)(h1 + (size_t)d * 256 + lane * 8);
        float4 v0 = __ldg(hp), v1 = __ldg(hp + 1);
        acc[0]=aself_h*v0.x; acc[1]=aself_h*v0.y; acc[2]=aself_h*v0.z; acc[3]=aself_h*v0.w;
        acc[4]=aself_h*v1.x; acc[5]=aself_h*v1.y; acc[6]=aself_h*v1.z; acc[7]=aself_h*v1.w;
    }
    for (int e = 0; e < deg; e++) {
        int s = __ldg(col + beg + e);
        float w = (e < WCAP) ? s_w[warp][e * 4 + head]
                             : __expf(lrelu(__ldg(asrc + (size_t)s * 4 + head) + ad_head));
        float alpha = w * inv_h;
        const float4* hp = (const float4*)(h1 + (size_t)s * 256 + lane * 8);
        float4 v0 = __ldg(hp), v1 = __ldg(hp + 1);
        acc[0]+=alpha*v0.x; acc[1]+=alpha*v0.y; acc[2]+=alpha*v0.z; acc[3]+=alpha*v0.w;
        acc[4]+=alpha*v1.x; acc[5]+=alpha*v1.y; acc[6]+=alpha*v1.z; acc[7]+=alpha*v1.w;
    }
    const float4* bp = (const float4*)(bias + lane * 8);
    float4 b0 = __ldg(bp), b1v = __ldg(bp + 1);
    float4 o0, o1;
    o0.x=elu(acc[0]+b0.x);  o0.y=elu(acc[1]+b0.y);  o0.z=elu(acc[2]+b0.z);  o0.w=elu(acc[3]+b0.w);
    o1.x=elu(acc[4]+b1v.x); o1.y=elu(acc[5]+b1v.y); o1.z=elu(acc[6]+b1v.z); o1.w=elu(acc[7]+b1v.w);
    float4* op = (float4*)(out + (size_t)d * 256 + lane * 8);
    op[0] = o0; op[1] = o1;
}

// ---------------------------------------------------------------------------
// Layer-2 GAT gather + final epilogue.
// ---------------------------------------------------------------------------
__global__ __launch_bounds__(256) void gather2_kernel(
    const int* __restrict__ rp, const int* __restrict__ col,
    const float* __restrict__ h2,
    const float* __restrict__ asrc, const float* __restrict__ adst,
    const float* __restrict__ b2, const float* __restrict__ Ws,
    const float* __restrict__ bs, float* __restrict__ out, int N)
{
    __shared__ float s_w[8][WCAP];
    int warp = threadIdx.x >> 5, lane = threadIdx.x & 31;
    int d = blockIdx.x * 8 + warp;
    if (d >= N) return;

    int beg = rp[d];
    int deg = rp[d + 1] - beg;
    float adv = __ldg(adst + d);

    float pden = 0.f;
    for (int e = lane; e < deg; e += 32) {
        int s = __ldg(col + beg + e);
        float w = __expf(lrelu(__ldg(asrc + s) + adv));
        if (e < WCAP) s_w[warp][e] = w;
        pden += w;
    }
#pragma unroll
    for (int off = 16; off; off >>= 1) pden += __shfl_xor_sync(0xffffffffu, pden, off);
    float w_self = __expf(lrelu(__ldg(asrc + d) + adv));
    float inv_den = 1.f / (pden + w_self + 1e-16f);
    __syncwarp();

    float2 acc;
    {
        float2 v = __ldg((const float2*)(h2 + (size_t)d * 64) + lane);
        float a = w_self * inv_den;
        acc.x = a * v.x; acc.y = a * v.y;
    }
    for (int e = 0; e < deg; e++) {
        int s = __ldg(col + beg + e);
        float w = (e < WCAP) ? s_w[warp][e]
                             : __expf(lrelu(__ldg(asrc + s) + adv));
        float alpha = w * inv_den;
        float2 v = __ldg((const float2*)(h2 + (size_t)s * 64) + lane);
        acc.x += alpha * v.x; acc.y += alpha * v.y;
    }
    float o0 = elu(acc.x + __ldg(b2 + lane * 2));
    float o1 = elu(acc.y + __ldg(b2 + lane * 2 + 1));
    *(float2*)(out + (size_t)d * 64 + lane * 2) = make_float2(o0, o1);
    float sc = o0 * __ldg(Ws + lane * 2) + o1 * __ldg(Ws + lane * 2 + 1);
#pragma unroll
    for (int off = 16; off; off >>= 1) sc += __shfl_xor_sync(0xffffffffu, sc, off);
    if (lane == 0) out[(size_t)N * 64 + d] = sc + __ldg(bs);
}

// ---------------------------------------------------------------------------
// Launch: CSR build forked onto a side stream, overlapping layer-1 GEMM.
// ---------------------------------------------------------------------------
extern "C" void kernel_launch(void* const* d_in, const int* in_sizes, int n_in,
                              void* d_out, int out_size)
{
    const float* x   = (const float*)d_in[0];
    const int*   ei  = (const int*)d_in[1];
    const float* W1  = (const float*)d_in[2];
    const float* as1 = (const float*)d_in[3];
    const float* ad1 = (const float*)d_in[4];
    const float* b1  = (const float*)d_in[5];
    const float* W2  = (const float*)d_in[6];
    const float* as2 = (const float*)d_in[7];
    const float* ad2 = (const float*)d_in[8];
    const float* b2  = (const float*)d_in[9];
    const float* Ws  = (const float*)d_in[10];
    const float* bs  = (const float*)d_in[11];
    float*       out = (float*)d_out;

    const int N = in_sizes[0] / 128;
    const int E = in_sizes[1] / 2;

    float *h1, *hm, *h2, *as1p, *ad1p, *as2p, *ad2p;
    int *cnt, *rp, *cur, *colp;
    cudaGetSymbolAddress((void**)&h1,   g_h1);
    cudaGetSymbolAddress((void**)&hm,   g_hm);
    cudaGetSymbolAddress((void**)&h2,   g_h2);
    cudaGetSymbolAddress((void**)&as1p, g_as1);
    cudaGetSymbolAddress((void**)&ad1p, g_ad1);
    cudaGetSymbolAddress((void**)&as2p, g_as2);
    cudaGetSymbolAddress((void**)&ad2p, g_ad2);
    cudaGetSymbolAddress((void**)&cnt,  g_cnt);
    cudaGetSymbolAddress((void**)&rp,   g_rp);
    cudaGetSymbolAddress((void**)&cur,  g_cur);
    cudaGetSymbolAddress((void**)&colp, g_col);

    static cudaStream_t s2 = nullptr;
    static cudaEvent_t evFork = nullptr, evJoin = nullptr;
    if (!s2) {
        cudaStreamCreateWithFlags(&s2, cudaStreamNonBlocking);
        cudaEventCreateWithFlags(&evFork, cudaEventDisableTiming);
        cudaEventCreateWithFlags(&evJoin, cudaEventDisableTiming);
    }

    // Fork: CSR build on s2, concurrent with layer-1 GEMM on the main stream.
    cudaEventRecord(evFork, 0);
    cudaStreamWaitEvent(s2, evFork, 0);
    cudaMemsetAsync(cnt, 0, (size_t)N * sizeof(int), s2);
    count_kernel<<<(E + 255) / 256, 256, 0, s2>>>(ei, cnt, E);
    scan_kernel<<<1, 1024, 0, s2>>>(cnt, rp, cur, N);
    fill_kernel<<<(E + 255) / 256, 256, 0, s2>>>(ei, cur, colp, E);
    cudaEventRecord(evJoin, s2);

    // Layer 1 GEMM + fused attention scalars (heads = block columns)
    tf32_gemm<<<dim3(4, (N + 127) / 128), 256>>>(
        N, 256, 128, x, W1, h1, as1, ad1, as1p, ad1p, 4);

    // Join: gather needs CSR + GEMM outputs
    cudaStreamWaitEvent(0, evJoin, 0);
    gather1_kernel<<<(N + 7) / 8, 256>>>(rp, colp, h1, as1p, ad1p, b1, hm, N);

    // Layer 2
    tf32_gemm<<<dim3(1, (N + 127) / 128), 256>>>(
        N, 64, 256, hm, W2, h2, as2, ad2, as2p, ad2p, 1);
    gather2_kernel<<<(N + 7) / 8, 256>>>(rp, colp, h2, as2p, ad2p, b2, Ws, bs, out, N);
}

// round 8
// speedup vs baseline: 2.3208x; 1.1576x over previous
#include <cuda_runtime.h>
#include <cstdint>

// ---------------------------------------------------------------------------
// Fixed dataset: N=50000, E=800000, IN=128, L1: 4 heads x 64, L2: 1 head x 64.
// edge_index is int32: ei[0:E]=src, ei[E:2E]=dst. Self-loops handled in-warp.
// ---------------------------------------------------------------------------
#define NMAX 50000
#define EMAX 810000

__device__ __align__(16) float g_h1 [NMAX * 256];  // layer1 linear output
__device__ __align__(16) float g_hm [NMAX * 256];  // layer1 GAT output (tf32-rounded)
__device__ __align__(16) float g_h2 [NMAX * 64];   // layer2 linear output
__device__ __align__(16) float g_xt [NMAX * 128];  // x rounded to tf32
__device__ __align__(16) float g_w1t[128 * 256];
__device__ __align__(16) float g_w2t[256 * 64];
__device__ __align__(16) float g_as1[NMAX * 4];
__device__ __align__(16) float g_ad1[NMAX * 4];
__device__ __align__(16) float g_as2[NMAX];
__device__ __align__(16) float g_ad2[NMAX];
// CSR by dst
__device__ int g_cnt [NMAX];
__device__ int g_rp  [NMAX + 1];
__device__ int g_cur [NMAX];
__device__ int g_col [EMAX];

__device__ __forceinline__ float lrelu(float x) { return x > 0.f ? x : 0.2f * x; }
__device__ __forceinline__ float elu(float x)   { return x > 0.f ? x : expm1f(x); }
__device__ __forceinline__ uint32_t to_tf32(float x) {
    uint32_t r;
    asm("cvt.rna.tf32.f32 %0, %1;" : "=r"(r) : "f"(x));
    return r;
}
__device__ __forceinline__ float tf32f(float x) { return __uint_as_float(to_tf32(x)); }
__device__ __forceinline__ void cp16(uint32_t saddr, const void* gaddr) {
    asm volatile("cp.async.cg.shared.global [%0], [%1], 16;" :: "r"(saddr), "l"(gaddr));
}
__device__ __forceinline__ uint32_t sm_u32(const void* p) {
    return (uint32_t)__cvta_generic_to_shared(p);
}

// ---------------------------------------------------------------------------
// Pre-round x, W1, W2 to tf32-canonical fp32 (element counts divisible by 4)
// ---------------------------------------------------------------------------
__global__ void cvt3_kernel(const float* __restrict__ x,  float* __restrict__ xt,  int nx4,
                            const float* __restrict__ w1, float* __restrict__ w1t, int n14,
                            const float* __restrict__ w2, float* __restrict__ w2t, int n24)
{
    int i = blockIdx.x * blockDim.x + threadIdx.x;
    int stride = gridDim.x * blockDim.x;
    for (int j = i; j < nx4; j += stride) {
        float4 v = ((const float4*)x)[j];
        ((float4*)xt)[j] = make_float4(tf32f(v.x), tf32f(v.y), tf32f(v.z), tf32f(v.w));
    }
    for (int j = i; j < n14; j += stride) {
        float4 v = ((const float4*)w1)[j];
        ((float4*)w1t)[j] = make_float4(tf32f(v.x), tf32f(v.y), tf32f(v.z), tf32f(v.w));
    }
    for (int j = i; j < n24; j += stride) {
        float4 v = ((const float4*)w2)[j];
        ((float4*)w2t)[j] = make_float4(tf32f(v.x), tf32f(v.y), tf32f(v.z), tf32f(v.w));
    }
}

// ---------------------------------------------------------------------------
// CSR build
// ---------------------------------------------------------------------------
__global__ void count_kernel(const int* __restrict__ ei, int* cnt, int E) {
    int e = blockIdx.x * blockDim.x + threadIdx.x;
    if (e < E) atomicAdd(cnt + ei[E + e], 1);
}

__global__ void scan_kernel(const int* __restrict__ cnt, int* rp, int* cur, int N) {
    __shared__ int sums[1024];
    int t = threadIdx.x;
    int C = (N + 1023) / 1024;
    int b0 = t * C, b1 = min(N, b0 + C);
    int s = 0;
    for (int i = b0; i < b1; i++) s += cnt[i];
    sums[t] = s;
    __syncthreads();
    for (int off = 1; off < 1024; off <<= 1) {
        int v = (t >= off) ? sums[t - off] : 0;
        __syncthreads();
        sums[t] += v;
        __syncthreads();
    }
    int run = (t == 0) ? 0 : sums[t - 1];
    for (int i = b0; i < b1; i++) { rp[i] = run; cur[i] = run; run += cnt[i]; }
    if (b0 < N && b1 == N) rp[N] = run;
}

__global__ void fill_kernel(const int* __restrict__ ei, int* cur, int* col, int E) {
    int e = blockIdx.x * blockDim.x + threadIdx.x;
    if (e >= E) return;
    int d = ei[E + e];
    int pos = atomicAdd(cur + d, 1);
    col[pos] = ei[e];
}

// ---------------------------------------------------------------------------
// TF32 GEMM, cp.async double-buffered. Inputs must be tf32-canonical fp32.
// C[M,Nc] = A[M,K] @ B[K,Nc]. Block 128x64, BK=32, 8 warps, warp tile 32x32.
// Fused attention-scalar epilogue (head = blockIdx.x, 64 channels).
// ---------------------------------------------------------------------------
#define AKP 36          // A smem row stride: banks (4r+c)%32 unique
#define BNP 72          // B smem row stride: banks (8k+n)%32 unique
#define A_STAGE (128 * AKP)
#define B_STAGE (32 * BNP)
#define STAGE   (A_STAGE + B_STAGE)
#define GEMM_SMEM (2 * STAGE * 4)

__global__ __launch_bounds__(256, 3) void tf32_gemm(
    int M, int Nc, int K,
    const float* __restrict__ A, const float* __restrict__ B, float* __restrict__ C,
    const float* __restrict__ att_s, const float* __restrict__ att_d,
    float* __restrict__ asrc, float* __restrict__ adst, int astride)
{
    extern __shared__ uint32_t smem[];
    __shared__ float s_ps[2][128];
    __shared__ float s_pd[2][128];

    const int tid    = threadIdx.x;
    const int lane   = tid & 31;
    const int wid    = tid >> 5;
    const int warp_m = wid & 3;
    const int warp_n = wid >> 2;
    const int bn0    = blockIdx.x * 64;
    const int bm0    = blockIdx.y * 128;

    float acc[2][4][4];
#pragma unroll
    for (int i = 0; i < 2; i++)
#pragma unroll
        for (int j = 0; j < 4; j++)
#pragma unroll
            for (int k = 0; k < 4; k++) acc[i][j][k] = 0.f;

    const int rA = lane >> 2;
    const int cA = lane & 3;

    // issue cp.async for tile k0 into stage p
    auto issue = [&](int k0, int p) {
        uint32_t* Asb = smem + p * STAGE;
        uint32_t* Bsb = Asb + A_STAGE;
#pragma unroll
        for (int t = 0; t < 4; t++) {
            int i = tid + t * 256, r = i >> 3, c = (i & 7) * 4;
            int gr = bm0 + r;
            if (gr < M) cp16(sm_u32(&Asb[r * AKP + c]), A + (size_t)gr * K + k0 + c);
            else        *(uint4*)&Asb[r * AKP + c] = make_uint4(0, 0, 0, 0);
        }
#pragma unroll
        for (int t = 0; t < 2; t++) {
            int i = tid + t * 256, r = i >> 4, c = (i & 15) * 4;
            cp16(sm_u32(&Bsb[r * BNP + c]), B + (size_t)(k0 + r) * Nc + bn0 + c);
        }
        asm volatile("cp.async.commit_group;");
    };

    const int T = K / 32;
    issue(0, 0);

    for (int t = 0; t < T; t++) {
        int p = t & 1;
        if (t + 1 < T) {
            issue((t + 1) * 32, 1 - p);
            asm volatile("cp.async.wait_group 1;");
        } else {
            asm volatile("cp.async.wait_group 0;");
        }
        __syncthreads();

        const uint32_t* Asb = smem + p * STAGE;
        const uint32_t* Bsb = Asb + A_STAGE;

#pragma unroll
        for (int kk = 0; kk < 32; kk += 8) {
            uint32_t a[2][4];
#pragma unroll
            for (int mf = 0; mf < 2; mf++) {
                int r0 = warp_m * 32 + mf * 16 + rA;
                a[mf][0] = Asb[(r0    ) * AKP + kk + cA];
                a[mf][1] = Asb[(r0 + 8) * AKP + kk + cA];
                a[mf][2] = Asb[(r0    ) * AKP + kk + cA + 4];
                a[mf][3] = Asb[(r0 + 8) * AKP + kk + cA + 4];
            }
            uint32_t b[4][2];
#pragma unroll
            for (int nf = 0; nf < 4; nf++) {
                int n0 = warp_n * 32 + nf * 8 + rA;
                b[nf][0] = Bsb[(kk + cA    ) * BNP + n0];
                b[nf][1] = Bsb[(kk + cA + 4) * BNP + n0];
            }
#pragma unroll
            for (int mf = 0; mf < 2; mf++)
#pragma unroll
                for (int nf = 0; nf < 4; nf++) {
                    asm volatile(
                        "mma.sync.aligned.m16n8k8.row.col.f32.tf32.tf32.f32 "
                        "{%0,%1,%2,%3}, {%4,%5,%6,%7}, {%8,%9}, {%0,%1,%2,%3};"
                        : "+f"(acc[mf][nf][0]), "+f"(acc[mf][nf][1]),
                          "+f"(acc[mf][nf][2]), "+f"(acc[mf][nf][3])
                        : "r"(a[mf][0]), "r"(a[mf][1]), "r"(a[mf][2]), "r"(a[mf][3]),
                          "r"(b[nf][0]), "r"(b[nf][1]));
                }
        }
        __syncthreads();
    }

    // Store C
#pragma unroll
    for (int mf = 0; mf < 2; mf++) {
        int r0 = bm0 + warp_m * 32 + mf * 16 + rA;
#pragma unroll
        for (int nf = 0; nf < 4; nf++) {
            int cc = bn0 + warp_n * 32 + nf * 8 + cA * 2;
            if (r0 < M)
                *(float2*)(C + (size_t)r0 * Nc + cc)
                    = make_float2(acc[mf][nf][0], acc[mf][nf][1]);
            if (r0 + 8 < M)
                *(float2*)(C + (size_t)(r0 + 8) * Nc + cc)
                    = make_float2(acc[mf][nf][2], acc[mf][nf][3]);
        }
    }

    // Fused attention scalars for head blockIdx.x (h without bias == acc)
    const int hb = blockIdx.x * 64;
    float ps[2][2] = {{0.f,0.f},{0.f,0.f}}, pd[2][2] = {{0.f,0.f},{0.f,0.f}};
#pragma unroll
    for (int mf = 0; mf < 2; mf++)
#pragma unroll
        for (int nf = 0; nf < 4; nf++) {
            int cloc = warp_n * 32 + nf * 8 + cA * 2;
            float a_s0 = __ldg(att_s + hb + cloc), a_s1 = __ldg(att_s + hb + cloc + 1);
            float a_d0 = __ldg(att_d + hb + cloc), a_d1 = __ldg(att_d + hb + cloc + 1);
            ps[mf][0] += acc[mf][nf][0] * a_s0 + acc[mf][nf][1] * a_s1;
            ps[mf][1] += acc[mf][nf][2] * a_s0 + acc[mf][nf][3] * a_s1;
            pd[mf][0] += acc[mf][nf][0] * a_d0 + acc[mf][nf][1] * a_d1;
            pd[mf][1] += acc[mf][nf][2] * a_d0 + acc[mf][nf][3] * a_d1;
        }
#pragma unroll
    for (int mf = 0; mf < 2; mf++)
#pragma unroll
        for (int hh = 0; hh < 2; hh++) {
            ps[mf][hh] += __shfl_xor_sync(0xffffffffu, ps[mf][hh], 1);
            ps[mf][hh] += __shfl_xor_sync(0xffffffffu, ps[mf][hh], 2);
            pd[mf][hh] += __shfl_xor_sync(0xffffffffu, pd[mf][hh], 1);
            pd[mf][hh] += __shfl_xor_sync(0xffffffffu, pd[mf][hh], 2);
        }
    if (cA == 0) {
#pragma unroll
        for (int mf = 0; mf < 2; mf++) {
            int r0 = warp_m * 32 + mf * 16 + rA;
            s_ps[warp_n][r0]     = ps[mf][0];
            s_ps[warp_n][r0 + 8] = ps[mf][1];
            s_pd[warp_n][r0]     = pd[mf][0];
            s_pd[warp_n][r0 + 8] = pd[mf][1];
        }
    }
    __syncthreads();
    if (tid < 128) {
        int gr = bm0 + tid;
        if (gr < M) {
            asrc[(size_t)gr * astride + blockIdx.x] = s_ps[0][tid] + s_ps[1][tid];
            adst[(size_t)gr * astride + blockIdx.x] = s_pd[0][tid] + s_pd[1][tid];
        }
    }
}

// ---------------------------------------------------------------------------
// Layer-1 GAT gather: one warp per dst node. Writes hm tf32-rounded
// (hm is consumed only by the layer-2 GEMM).
// ---------------------------------------------------------------------------
#define WCAP 128

__global__ __launch_bounds__(256) void gather1_kernel(
    const int* __restrict__ rp, const int* __restrict__ col,
    const float* __restrict__ h1,
    const float* __restrict__ asrc, const float* __restrict__ adst,
    const float* __restrict__ bias, float* __restrict__ out, int N)
{
    __shared__ float s_w[8][WCAP * 4];
    int warp = threadIdx.x >> 5, lane = threadIdx.x & 31;
    int d = blockIdx.x * 8 + warp;
    if (d >= N) return;

    int beg = rp[d];
    int deg = rp[d + 1] - beg;
    int hme = lane & 3;
    float ad_hme = __ldg(adst + (size_t)d * 4 + hme);

    float pden = 0.f;
    int npairs = deg * 4;
    for (int idx = lane; idx < npairs; idx += 32) {
        int e = idx >> 2;
        int s = __ldg(col + beg + e);
        float w = __expf(lrelu(__ldg(asrc + (size_t)s * 4 + hme) + ad_hme));
        if (e < WCAP) s_w[warp][idx] = w;
        pden += w;
    }
    pden += __shfl_xor_sync(0xffffffffu, pden, 4);
    pden += __shfl_xor_sync(0xffffffffu, pden, 8);
    pden += __shfl_xor_sync(0xffffffffu, pden, 16);
    float w_self = __expf(lrelu(__ldg(asrc + (size_t)d * 4 + hme) + ad_hme));
    float inv_den = 1.f / (pden + w_self + 1e-16f);
    __syncwarp();

    int head = lane >> 3;
    float inv_h   = __shfl_sync(0xffffffffu, inv_den, head);
    float aself_h = __shfl_sync(0xffffffffu, w_self,  head) * inv_h;
    float ad_head = __shfl_sync(0xffffffffu, ad_hme,  head);

    float acc[8];
    {
        const float4* hp = (const float4*)(h1 + (size_t)d * 256 + lane * 8);
        float4 v0 = __ldg(hp), v1 = __ldg(hp + 1);
        acc[0]=aself_h*v0.x; acc[1]=aself_h*v0.y; acc[2]=aself_h*v0.z; acc[3]=aself_h*v0.w;
        acc[4]=aself_h*v1.x; acc[5]=aself_h*v1.y; acc[6]=aself_h*v1.z; acc[7]=aself_h*v1.w;
    }
    int e = 0;
    for (; e + 2 <= deg; e += 2) {
        int s0 = __ldg(col + beg + e);
        int s1 = __ldg(col + beg + e + 1);
        float w0 = (e     < WCAP) ? s_w[warp][e * 4 + head]
                 : __expf(lrelu(__ldg(asrc + (size_t)s0 * 4 + head) + ad_head));
        float w1 = (e + 1 < WCAP) ? s_w[warp][(e + 1) * 4 + head]
                 : __expf(lrelu(__ldg(asrc + (size_t)s1 * 4 + head) + ad_head));
        float al0 = w0 * inv_h, al1 = w1 * inv_h;
        const float4* hp0 = (const float4*)(h1 + (size_t)s0 * 256 + lane * 8);
        const float4* hp1 = (const float4*)(h1 + (size_t)s1 * 256 + lane * 8);
        float4 u0 = __ldg(hp0), u1 = __ldg(hp0 + 1);
        float4 v0 = __ldg(hp1), v1 = __ldg(hp1 + 1);
        acc[0]+=al0*u0.x; acc[1]+=al0*u0.y; acc[2]+=al0*u0.z; acc[3]+=al0*u0.w;
        acc[4]+=al0*u1.x; acc[5]+=al0*u1.y; acc[6]+=al0*u1.z; acc[7]+=al0*u1.w;
        acc[0]+=al1*v0.x; acc[1]+=al1*v0.y; acc[2]+=al1*v0.z; acc[3]+=al1*v0.w;
        acc[4]+=al1*v1.x; acc[5]+=al1*v1.y; acc[6]+=al1*v1.z; acc[7]+=al1*v1.w;
    }
    for (; e < deg; e++) {
        int s = __ldg(col + beg + e);
        float w = (e < WCAP) ? s_w[warp][e * 4 + head]
                             : __expf(lrelu(__ldg(asrc + (size_t)s * 4 + head) + ad_head));
        float alpha = w * inv_h;
        const float4* hp = (const float4*)(h1 + (size_t)s * 256 + lane * 8);
        float4 v0 = __ldg(hp), v1 = __ldg(hp + 1);
        acc[0]+=alpha*v0.x; acc[1]+=alpha*v0.y; acc[2]+=alpha*v0.z; acc[3]+=alpha*v0.w;
        acc[4]+=alpha*v1.x; acc[5]+=alpha*v1.y; acc[6]+=alpha*v1.z; acc[7]+=alpha*v1.w;
    }
    const float4* bp = (const float4*)(bias + lane * 8);
    float4 b0 = __ldg(bp), b1v = __ldg(bp + 1);
    float4 o0, o1;
    o0.x=tf32f(elu(acc[0]+b0.x));  o0.y=tf32f(elu(acc[1]+b0.y));
    o0.z=tf32f(elu(acc[2]+b0.z));  o0.w=tf32f(elu(acc[3]+b0.w));
    o1.x=tf32f(elu(acc[4]+b1v.x)); o1.y=tf32f(elu(acc[5]+b1v.y));
    o1.z=tf32f(elu(acc[6]+b1v.z)); o1.w=tf32f(elu(acc[7]+b1v.w));
    float4* op = (float4*)(out + (size_t)d * 256 + lane * 8);
    op[0] = o0; op[1] = o1;
}

// ---------------------------------------------------------------------------
// Layer-2 GAT gather + final epilogue.
// ---------------------------------------------------------------------------
__global__ __launch_bounds__(256) void gather2_kernel(
    const int* __restrict__ rp, const int* __restrict__ col,
    const float* __restrict__ h2,
    const float* __restrict__ asrc, const float* __restrict__ adst,
    const float* __restrict__ b2, const float* __restrict__ Ws,
    const float* __restrict__ bs, float* __restrict__ out, int N)
{
    __shared__ float s_w[8][WCAP];
    int warp = threadIdx.x >> 5, lane = threadIdx.x & 31;
    int d = blockIdx.x * 8 + warp;
    if (d >= N) return;

    int beg = rp[d];
    int deg = rp[d + 1] - beg;
    float adv = __ldg(adst + d);

    float pden = 0.f;
    for (int e = lane; e < deg; e += 32) {
        int s = __ldg(col + beg + e);
        float w = __expf(lrelu(__ldg(asrc + s) + adv));
        if (e < WCAP) s_w[warp][e] = w;
        pden += w;
    }
#pragma unroll
    for (int off = 16; off; off >>= 1) pden += __shfl_xor_sync(0xffffffffu, pden, off);
    float w_self = __expf(lrelu(__ldg(asrc + d) + adv));
    float inv_den = 1.f / (pden + w_self + 1e-16f);
    __syncwarp();

    float2 acc;
    {
        float2 v = __ldg((const float2*)(h2 + (size_t)d * 64) + lane);
        float a = w_self * inv_den;
        acc.x = a * v.x; acc.y = a * v.y;
    }
    for (int e = 0; e < deg; e++) {
        int s = __ldg(col + beg + e);
        float w = (e < WCAP) ? s_w[warp][e]
                             : __expf(lrelu(__ldg(asrc + s) + adv));
        float alpha = w * inv_den;
        float2 v = __ldg((const float2*)(h2 + (size_t)s * 64) + lane);
        acc.x += alpha * v.x; acc.y += alpha * v.y;
    }
    float o0 = elu(acc.x + __ldg(b2 + lane * 2));
    float o1 = elu(acc.y + __ldg(b2 + lane * 2 + 1));
    *(float2*)(out + (size_t)d * 64 + lane * 2) = make_float2(o0, o1);
    float sc = o0 * __ldg(Ws + lane * 2) + o1 * __ldg(Ws + lane * 2 + 1);
#pragma unroll
    for (int off = 16; off; off >>= 1) sc += __shfl_xor_sync(0xffffffffu, sc, off);
    if (lane == 0) out[(size_t)N * 64 + d] = sc + __ldg(bs);
}

// ---------------------------------------------------------------------------
// Launch: CSR build on side stream overlaps cvt3 + layer-1 GEMM.
// ---------------------------------------------------------------------------
extern "C" void kernel_launch(void* const* d_in, const int* in_sizes, int n_in,
                              void* d_out, int out_size)
{
    const float* x   = (const float*)d_in[0];
    const int*   ei  = (const int*)d_in[1];
    const float* W1  = (const float*)d_in[2];
    const float* as1 = (const float*)d_in[3];
    const float* ad1 = (const float*)d_in[4];
    const float* b1  = (const float*)d_in[5];
    const float* W2  = (const float*)d_in[6];
    const float* as2 = (const float*)d_in[7];
    const float* ad2 = (const float*)d_in[8];
    const float* b2  = (const float*)d_in[9];
    const float* Ws  = (const float*)d_in[10];
    const float* bs  = (const float*)d_in[11];
    float*       out = (float*)d_out;

    const int N = in_sizes[0] / 128;
    const int E = in_sizes[1] / 2;

    float *h1, *hm, *h2, *xt, *w1t, *w2t, *as1p, *ad1p, *as2p, *ad2p;
    int *cnt, *rp, *cur, *colp;
    cudaGetSymbolAddress((void**)&h1,   g_h1);
    cudaGetSymbolAddress((void**)&hm,   g_hm);
    cudaGetSymbolAddress((void**)&h2,   g_h2);
    cudaGetSymbolAddress((void**)&xt,   g_xt);
    cudaGetSymbolAddress((void**)&w1t,  g_w1t);
    cudaGetSymbolAddress((void**)&w2t,  g_w2t);
    cudaGetSymbolAddress((void**)&as1p, g_as1);
    cudaGetSymbolAddress((void**)&ad1p, g_ad1);
    cudaGetSymbolAddress((void**)&as2p, g_as2);
    cudaGetSymbolAddress((void**)&ad2p, g_ad2);
    cudaGetSymbolAddress((void**)&cnt,  g_cnt);
    cudaGetSymbolAddress((void**)&rp,   g_rp);
    cudaGetSymbolAddress((void**)&cur,  g_cur);
    cudaGetSymbolAddress((void**)&colp, g_col);

    static cudaStream_t s2 = nullptr;
    static cudaEvent_t evFork = nullptr, evJoin = nullptr;
    static bool attrSet = false;
    if (!s2) {
        cudaStreamCreateWithFlags(&s2, cudaStreamNonBlocking);
        cudaEventCreateWithFlags(&evFork, cudaEventDisableTiming);
        cudaEventCreateWithFlags(&evJoin, cudaEventDisableTiming);
    }
    if (!attrSet) {
        cudaFuncSetAttribute(tf32_gemm,
                             cudaFuncAttributeMaxDynamicSharedMemorySize, GEMM_SMEM);
        attrSet = true;
    }

    // Fork: CSR build on s2, concurrent with cvt3 + layer-1 GEMM.
    cudaEventRecord(evFork, 0);
    cudaStreamWaitEvent(s2, evFork, 0);
    cudaMemsetAsync(cnt, 0, (size_t)N * sizeof(int), s2);
    count_kernel<<<(E + 255) / 256, 256, 0, s2>>>(ei, cnt, E);
    scan_kernel<<<1, 1024, 0, s2>>>(cnt, rp, cur, N);
    fill_kernel<<<(E + 255) / 256, 256, 0, s2>>>(ei, cur, colp, E);
    cudaEventRecord(evJoin, s2);

    // Pre-round GEMM operands to canonical tf32
    cvt3_kernel<<<1024, 256>>>(x, xt, N * 128 / 4,
                               W1, w1t, 128 * 256 / 4,
                               W2, w2t, 256 * 64 / 4);

    // Layer 1 GEMM + fused attention scalars
    tf32_gemm<<<dim3(4, (N + 127) / 128), 256, GEMM_SMEM>>>(
        N, 256, 128, xt, w1t, h1, as1, ad1, as1p, ad1p, 4);

    cudaStreamWaitEvent(0, evJoin, 0);
    gather1_kernel<<<(N + 7) / 8, 256>>>(rp, colp, h1, as1p, ad1p, b1, hm, N);

    // Layer 2
    tf32_gemm<<<dim3(1, (N + 127) / 128), 256, GEMM_SMEM>>>(
        N, 64, 256, hm, w2t, h2, as2, ad2, as2p, ad2p, 1);
    gather2_kernel<<<(N + 7) / 8, 256>>>(rp, colp, h2, as2p, ad2p, b2, Ws, bs, out, N);
}

// round 9
// speedup vs baseline: 2.5130x; 1.0828x over previous
#include <cuda_runtime.h>
#include <cstdint>

// ---------------------------------------------------------------------------
// Fixed dataset: N=50000, E=800000, IN=128, L1: 4 heads x 64, L2: 1 head x 64.
// edge_index is int32: ei[0:E]=src, ei[E:2E]=dst. Self-loops handled in-warp.
// ---------------------------------------------------------------------------
#define NMAX 50000
#define EMAX 810000

__device__ __align__(16) float g_h1 [NMAX * 256];  // layer1 linear output
__device__ __align__(16) float g_hm [NMAX * 256];  // layer1 GAT output (tf32-rounded)
__device__ __align__(16) float g_h2 [NMAX * 64];   // layer2 linear output
__device__ __align__(16) float g_w1t[128 * 256];
__device__ __align__(16) float g_w2t[256 * 64];
__device__ __align__(16) float g_as1[NMAX * 4];
__device__ __align__(16) float g_ad1[NMAX * 4];
__device__ __align__(16) float g_as2[NMAX];
__device__ __align__(16) float g_ad2[NMAX];
// CSR by dst
__device__ int g_cnt [NMAX];
__device__ int g_rp  [NMAX + 1];
__device__ int g_cur [NMAX];
__device__ int g_col [EMAX];

__device__ __forceinline__ float lrelu(float x) { return x > 0.f ? x : 0.2f * x; }
__device__ __forceinline__ float elu(float x)   { return x > 0.f ? x : expm1f(x); }
__device__ __forceinline__ uint32_t to_tf32(float x) {
    uint32_t r;
    asm("cvt.rna.tf32.f32 %0, %1;" : "=r"(r) : "f"(x));
    return r;
}
__device__ __forceinline__ float tf32f(float x) { return __uint_as_float(to_tf32(x)); }
__device__ __forceinline__ void cp16(uint32_t saddr, const void* gaddr) {
    asm volatile("cp.async.cg.shared.global [%0], [%1], 16;" :: "r"(saddr), "l"(gaddr));
}
__device__ __forceinline__ uint32_t sm_u32(const void* p) {
    return (uint32_t)__cvta_generic_to_shared(p);
}

// ---------------------------------------------------------------------------
// Pre-round W1, W2 to tf32-canonical fp32 (small, ~2us)
// ---------------------------------------------------------------------------
__global__ void cvt_w_kernel(const float* __restrict__ w1, float* __restrict__ w1t, int n14,
                             const float* __restrict__ w2, float* __restrict__ w2t, int n24)
{
    int i = blockIdx.x * blockDim.x + threadIdx.x;
    int stride = gridDim.x * blockDim.x;
    for (int j = i; j < n14; j += stride) {
        float4 v = ((const float4*)w1)[j];
        ((float4*)w1t)[j] = make_float4(tf32f(v.x), tf32f(v.y), tf32f(v.z), tf32f(v.w));
    }
    for (int j = i; j < n24; j += stride) {
        float4 v = ((const float4*)w2)[j];
        ((float4*)w2t)[j] = make_float4(tf32f(v.x), tf32f(v.y), tf32f(v.z), tf32f(v.w));
    }
}

// ---------------------------------------------------------------------------
// CSR build
// ---------------------------------------------------------------------------
__global__ void count_kernel(const int* __restrict__ ei, int* cnt, int E) {
    int e = blockIdx.x * blockDim.x + threadIdx.x;
    if (e < E) atomicAdd(cnt + ei[E + e], 1);
}

__global__ void scan_kernel(const int* __restrict__ cnt, int* rp, int* cur, int N) {
    __shared__ int sums[1024];
    int t = threadIdx.x;
    int C = (N + 1023) / 1024;
    int b0 = t * C, b1 = min(N, b0 + C);
    int s = 0;
    for (int i = b0; i < b1; i++) s += cnt[i];
    sums[t] = s;
    __syncthreads();
    for (int off = 1; off < 1024; off <<= 1) {
        int v = (t >= off) ? sums[t - off] : 0;
        __syncthreads();
        sums[t] += v;
        __syncthreads();
    }
    int run = (t == 0) ? 0 : sums[t - 1];
    for (int i = b0; i < b1; i++) { rp[i] = run; cur[i] = run; run += cnt[i]; }
    if (b0 < N && b1 == N) rp[N] = run;
}

__global__ void fill_kernel(const int* __restrict__ ei, int* cur, int* col, int E) {
    int e = blockIdx.x * blockDim.x + threadIdx.x;
    if (e >= E) return;
    int d = ei[E + e];
    int pos = atomicAdd(cur + d, 1);
    col[pos] = ei[e];
}

// ---------------------------------------------------------------------------
// TF32 GEMM, cp.async double-buffered. B must be tf32-canonical fp32.
// CVTA: convert A tiles to tf32 (RNA) in smem after arrival (for raw-fp32 A).
// C[M,Nc] = A[M,K] @ B[K,Nc]. Block 128x64, BK=32, 8 warps, warp tile 32x32.
// Fused attention-scalar epilogue (head = blockIdx.x, 64 channels).
// ---------------------------------------------------------------------------
#define AKP 36
#define BNP 72
#define A_STAGE (128 * AKP)
#define B_STAGE (32 * BNP)
#define STAGE   (A_STAGE + B_STAGE)
#define GEMM_SMEM (2 * STAGE * 4)

template <bool CVTA>
__global__ __launch_bounds__(256, 3) void tf32_gemm(
    int M, int Nc, int K,
    const float* __restrict__ A, const float* __restrict__ B, float* __restrict__ C,
    const float* __restrict__ att_s, const float* __restrict__ att_d,
    float* __restrict__ asrc, float* __restrict__ adst, int astride)
{
    extern __shared__ uint32_t smem[];
    __shared__ float s_ps[2][128];
    __shared__ float s_pd[2][128];

    const int tid    = threadIdx.x;
    const int lane   = tid & 31;
    const int wid    = tid >> 5;
    const int warp_m = wid & 3;
    const int warp_n = wid >> 2;
    const int bn0    = blockIdx.x * 64;
    const int bm0    = blockIdx.y * 128;

    float acc[2][4][4];
#pragma unroll
    for (int i = 0; i < 2; i++)
#pragma unroll
        for (int j = 0; j < 4; j++)
#pragma unroll
            for (int k = 0; k < 4; k++) acc[i][j][k] = 0.f;

    const int rA = lane >> 2;
    const int cA = lane & 3;

    auto issue = [&](int k0, int p) {
        uint32_t* Asb = smem + p * STAGE;
        uint32_t* Bsb = Asb + A_STAGE;
#pragma unroll
        for (int t = 0; t < 4; t++) {
            int i = tid + t * 256, r = i >> 3, c = (i & 7) * 4;
            int gr = bm0 + r;
            if (gr < M) cp16(sm_u32(&Asb[r * AKP + c]), A + (size_t)gr * K + k0 + c);
            else        *(uint4*)&Asb[r * AKP + c] = make_uint4(0, 0, 0, 0);
        }
#pragma unroll
        for (int t = 0; t < 2; t++) {
            int i = tid + t * 256, r = i >> 4, c = (i & 15) * 4;
            cp16(sm_u32(&Bsb[r * BNP + c]), B + (size_t)(k0 + r) * Nc + bn0 + c);
        }
        asm volatile("cp.async.commit_group;");
    };

    const int T = K / 32;
    issue(0, 0);

    for (int t = 0; t < T; t++) {
        int p = t & 1;
        if (t + 1 < T) {
            issue((t + 1) * 32, 1 - p);
            asm volatile("cp.async.wait_group 1;");
        } else {
            asm volatile("cp.async.wait_group 0;");
        }
        __syncthreads();

        uint32_t* Asb = smem + p * STAGE;
        const uint32_t* Bsb = Asb + A_STAGE;

        if (CVTA) {
            // Round this stage's A tile to tf32 in place (same slots this
            // thread cp.async'd; next stage targets the other buffer).
#pragma unroll
            for (int tt = 0; tt < 4; tt++) {
                int i = tid + tt * 256, r = i >> 3, c = (i & 7) * 4;
                uint4 u = *(uint4*)&Asb[r * AKP + c];
                u.x = to_tf32(__uint_as_float(u.x));
                u.y = to_tf32(__uint_as_float(u.y));
                u.z = to_tf32(__uint_as_float(u.z));
                u.w = to_tf32(__uint_as_float(u.w));
                *(uint4*)&Asb[r * AKP + c] = u;
            }
            __syncthreads();
        }

#pragma unroll
        for (int kk = 0; kk < 32; kk += 8) {
            uint32_t a[2][4];
#pragma unroll
            for (int mf = 0; mf < 2; mf++) {
                int r0 = warp_m * 32 + mf * 16 + rA;
                a[mf][0] = Asb[(r0    ) * AKP + kk + cA];
                a[mf][1] = Asb[(r0 + 8) * AKP + kk + cA];
                a[mf][2] = Asb[(r0    ) * AKP + kk + cA + 4];
                a[mf][3] = Asb[(r0 + 8) * AKP + kk + cA + 4];
            }
            uint32_t b[4][2];
#pragma unroll
            for (int nf = 0; nf < 4; nf++) {
                int n0 = warp_n * 32 + nf * 8 + rA;
                b[nf][0] = Bsb[(kk + cA    ) * BNP + n0];
                b[nf][1] = Bsb[(kk + cA + 4) * BNP + n0];
            }
#pragma unroll
            for (int mf = 0; mf < 2; mf++)
#pragma unroll
                for (int nf = 0; nf < 4; nf++) {
                    asm volatile(
                        "mma.sync.aligned.m16n8k8.row.col.f32.tf32.tf32.f32 "
                        "{%0,%1,%2,%3}, {%4,%5,%6,%7}, {%8,%9}, {%0,%1,%2,%3};"
                        : "+f"(acc[mf][nf][0]), "+f"(acc[mf][nf][1]),
                          "+f"(acc[mf][nf][2]), "+f"(acc[mf][nf][3])
                        : "r"(a[mf][0]), "r"(a[mf][1]), "r"(a[mf][2]), "r"(a[mf][3]),
                          "r"(b[nf][0]), "r"(b[nf][1]));
                }
        }
        __syncthreads();
    }

    // Store C
#pragma unroll
    for (int mf = 0; mf < 2; mf++) {
        int r0 = bm0 + warp_m * 32 + mf * 16 + rA;
#pragma unroll
        for (int nf = 0; nf < 4; nf++) {
            int cc = bn0 + warp_n * 32 + nf * 8 + cA * 2;
            if (r0 < M)
                *(float2*)(C + (size_t)r0 * Nc + cc)
                    = make_float2(acc[mf][nf][0], acc[mf][nf][1]);
            if (r0 + 8 < M)
                *(float2*)(C + (size_t)(r0 + 8) * Nc + cc)
                    = make_float2(acc[mf][nf][2], acc[mf][nf][3]);
        }
    }

    // Fused attention scalars for head blockIdx.x
    const int hb = blockIdx.x * 64;
    float ps[2][2] = {{0.f,0.f},{0.f,0.f}}, pd[2][2] = {{0.f,0.f},{0.f,0.f}};
#pragma unroll
    for (int mf = 0; mf < 2; mf++)
#pragma unroll
        for (int nf = 0; nf < 4; nf++) {
            int cloc = warp_n * 32 + nf * 8 + cA * 2;
            float a_s0 = __ldg(att_s + hb + cloc), a_s1 = __ldg(att_s + hb + cloc + 1);
            float a_d0 = __ldg(att_d + hb + cloc), a_d1 = __ldg(att_d + hb + cloc + 1);
            ps[mf][0] += acc[mf][nf][0] * a_s0 + acc[mf][nf][1] * a_s1;
            ps[mf][1] += acc[mf][nf][2] * a_s0 + acc[mf][nf][3] * a_s1;
            pd[mf][0] += acc[mf][nf][0] * a_d0 + acc[mf][nf][1] * a_d1;
            pd[mf][1] += acc[mf][nf][2] * a_d0 + acc[mf][nf][3] * a_d1;
        }
#pragma unroll
    for (int mf = 0; mf < 2; mf++)
#pragma unroll
        for (int hh = 0; hh < 2; hh++) {
            ps[mf][hh] += __shfl_xor_sync(0xffffffffu, ps[mf][hh], 1);
            ps[mf][hh] += __shfl_xor_sync(0xffffffffu, ps[mf][hh], 2);
            pd[mf][hh] += __shfl_xor_sync(0xffffffffu, pd[mf][hh], 1);
            pd[mf][hh] += __shfl_xor_sync(0xffffffffu, pd[mf][hh], 2);
        }
    if (cA == 0) {
#pragma unroll
        for (int mf = 0; mf < 2; mf++) {
            int r0 = warp_m * 32 + mf * 16 + rA;
            s_ps[warp_n][r0]     = ps[mf][0];
            s_ps[warp_n][r0 + 8] = ps[mf][1];
            s_pd[warp_n][r0]     = pd[mf][0];
            s_pd[warp_n][r0 + 8] = pd[mf][1];
        }
    }
    __syncthreads();
    if (tid < 128) {
        int gr = bm0 + tid;
        if (gr < M) {
            asrc[(size_t)gr * astride + blockIdx.x] = s_ps[0][tid] + s_ps[1][tid];
            adst[(size_t)gr * astride + blockIdx.x] = s_pd[0][tid] + s_pd[1][tid];
        }
    }
}

// ---------------------------------------------------------------------------
// Layer-1 GAT gather: one warp per dst node. Column indices + weights cached
// in smem during phase A; phase B 4-way unrolled for MLP.
// ---------------------------------------------------------------------------
#define WCAP 128

__global__ __launch_bounds__(256) void gather1_kernel(
    const int* __restrict__ rp, const int* __restrict__ col,
    const float* __restrict__ h1,
    const float* __restrict__ asrc, const float* __restrict__ adst,
    const float* __restrict__ bias, float* __restrict__ out, int N)
{
    __shared__ float s_w[8][WCAP * 4];
    __shared__ int   s_col[8][WCAP];
    int warp = threadIdx.x >> 5, lane = threadIdx.x & 31;
    int d = blockIdx.x * 8 + warp;
    if (d >= N) return;

    int beg = rp[d];
    int deg = rp[d + 1] - beg;
    int hme = lane & 3;
    float ad_hme = __ldg(adst + (size_t)d * 4 + hme);

    float pden = 0.f;
    int npairs = deg * 4;
    for (int idx = lane; idx < npairs; idx += 32) {
        int e = idx >> 2;
        int s = __ldg(col + beg + e);
        float w = __expf(lrelu(__ldg(asrc + (size_t)s * 4 + hme) + ad_hme));
        if (e < WCAP) {
            s_w[warp][idx] = w;
            if (hme == 0) s_col[warp][e] = s;
        }
        pden += w;
    }
    pden += __shfl_xor_sync(0xffffffffu, pden, 4);
    pden += __shfl_xor_sync(0xffffffffu, pden, 8);
    pden += __shfl_xor_sync(0xffffffffu, pden, 16);
    float w_self = __expf(lrelu(__ldg(asrc + (size_t)d * 4 + hme) + ad_hme));
    float inv_den = 1.f / (pden + w_self + 1e-16f);
    __syncwarp();

    int head = lane >> 3;
    float inv_h   = __shfl_sync(0xffffffffu, inv_den, head);
    float aself_h = __shfl_sync(0xffffffffu, w_self,  head) * inv_h;
    float ad_head = __shfl_sync(0xffffffffu, ad_hme,  head);

    float acc[8];
    {
        const float4* hp = (const float4*)(h1 + (size_t)d * 256 + lane * 8);
        float4 v0 = __ldg(hp), v1 = __ldg(hp + 1);
        acc[0]=aself_h*v0.x; acc[1]=aself_h*v0.y; acc[2]=aself_h*v0.z; acc[3]=aself_h*v0.w;
        acc[4]=aself_h*v1.x; acc[5]=aself_h*v1.y; acc[6]=aself_h*v1.z; acc[7]=aself_h*v1.w;
    }

    if (deg <= WCAP) {
        int e = 0;
        for (; e + 4 <= deg; e += 4) {
            int   sx[4];
            float al[4];
#pragma unroll
            for (int q = 0; q < 4; q++) {
                sx[q] = s_col[warp][e + q];
                al[q] = s_w[warp][(e + q) * 4 + head] * inv_h;
            }
            float4 u0[4], u1[4];
#pragma unroll
            for (int q = 0; q < 4; q++) {
                const float4* hp = (const float4*)(h1 + (size_t)sx[q] * 256 + lane * 8);
                u0[q] = __ldg(hp); u1[q] = __ldg(hp + 1);
            }
#pragma unroll
            for (int q = 0; q < 4; q++) {
                acc[0]+=al[q]*u0[q].x; acc[1]+=al[q]*u0[q].y;
                acc[2]+=al[q]*u0[q].z; acc[3]+=al[q]*u0[q].w;
                acc[4]+=al[q]*u1[q].x; acc[5]+=al[q]*u1[q].y;
                acc[6]+=al[q]*u1[q].z; acc[7]+=al[q]*u1[q].w;
            }
        }
        for (; e < deg; e++) {
            int s = s_col[warp][e];
            float alpha = s_w[warp][e * 4 + head] * inv_h;
            const float4* hp = (const float4*)(h1 + (size_t)s * 256 + lane * 8);
            float4 v0 = __ldg(hp), v1 = __ldg(hp + 1);
            acc[0]+=alpha*v0.x; acc[1]+=alpha*v0.y; acc[2]+=alpha*v0.z; acc[3]+=alpha*v0.w;
            acc[4]+=alpha*v1.x; acc[5]+=alpha*v1.y; acc[6]+=alpha*v1.z; acc[7]+=alpha*v1.w;
        }
    } else {
        for (int e = 0; e < deg; e++) {
            int s = __ldg(col + beg + e);
            float w = (e < WCAP) ? s_w[warp][e * 4 + head]
                                 : __expf(lrelu(__ldg(asrc + (size_t)s * 4 + head) + ad_head));
            float alpha = w * inv_h;
            const float4* hp = (const float4*)(h1 + (size_t)s * 256 + lane * 8);
            float4 v0 = __ldg(hp), v1 = __ldg(hp + 1);
            acc[0]+=alpha*v0.x; acc[1]+=alpha*v0.y; acc[2]+=alpha*v0.z; acc[3]+=alpha*v0.w;
            acc[4]+=alpha*v1.x; acc[5]+=alpha*v1.y; acc[6]+=alpha*v1.z; acc[7]+=alpha*v1.w;
        }
    }

    const float4* bp = (const float4*)(bias + lane * 8);
    float4 b0 = __ldg(bp), b1v = __ldg(bp + 1);
    float4 o0, o1;
    o0.x=tf32f(elu(acc[0]+b0.x));  o0.y=tf32f(elu(acc[1]+b0.y));
    o0.z=tf32f(elu(acc[2]+b0.z));  o0.w=tf32f(elu(acc[3]+b0.w));
    o1.x=tf32f(elu(acc[4]+b1v.x)); o1.y=tf32f(elu(acc[5]+b1v.y));
    o1.z=tf32f(elu(acc[6]+b1v.z)); o1.w=tf32f(elu(acc[7]+b1v.w));
    float4* op = (float4*)(out + (size_t)d * 256 + lane * 8);
    op[0] = o0; op[1] = o1;
}

// ---------------------------------------------------------------------------
// Layer-2 GAT gather + final epilogue.
// ---------------------------------------------------------------------------
__global__ __launch_bounds__(256) void gather2_kernel(
    const int* __restrict__ rp, const int* __restrict__ col,
    const float* __restrict__ h2,
    const float* __restrict__ asrc, const float* __restrict__ adst,
    const float* __restrict__ b2, const float* __restrict__ Ws,
    const float* __restrict__ bs, float* __restrict__ out, int N)
{
    __shared__ float s_w[8][WCAP];
    __shared__ int   s_col[8][WCAP];
    int warp = threadIdx.x >> 5, lane = threadIdx.x & 31;
    int d = blockIdx.x * 8 + warp;
    if (d >= N) return;

    int beg = rp[d];
    int deg = rp[d + 1] - beg;
    float adv = __ldg(adst + d);

    float pden = 0.f;
    for (int e = lane; e < deg; e += 32) {
        int s = __ldg(col + beg + e);
        float w = __expf(lrelu(__ldg(asrc + s) + adv));
        if (e < WCAP) { s_w[warp][e] = w; s_col[warp][e] = s; }
        pden += w;
    }
#pragma unroll
    for (int off = 16; off; off >>= 1) pden += __shfl_xor_sync(0xffffffffu, pden, off);
    float w_self = __expf(lrelu(__ldg(asrc + d) + adv));
    float inv_den = 1.f / (pden + w_self + 1e-16f);
    __syncwarp();

    float2 acc;
    {
        float2 v = __ldg((const float2*)(h2 + (size_t)d * 64) + lane);
        float a = w_self * inv_den;
        acc.x = a * v.x; acc.y = a * v.y;
    }
    if (deg <= WCAP) {
        int e = 0;
        for (; e + 4 <= deg; e += 4) {
            int sx[4]; float al[4]; float2 v[4];
#pragma unroll
            for (int q = 0; q < 4; q++) {
                sx[q] = s_col[warp][e + q];
                al[q] = s_w[warp][e + q] * inv_den;
            }
#pragma unroll
            for (int q = 0; q < 4; q++)
                v[q] = __ldg((const float2*)(h2 + (size_t)sx[q] * 64) + lane);
#pragma unroll
            for (int q = 0; q < 4; q++) {
                acc.x += al[q] * v[q].x; acc.y += al[q] * v[q].y;
            }
        }
        for (; e < deg; e++) {
            int s = s_col[warp][e];
            float alpha = s_w[warp][e] * inv_den;
            float2 v = __ldg((const float2*)(h2 + (size_t)s * 64) + lane);
            acc.x += alpha * v.x; acc.y += alpha * v.y;
        }
    } else {
        for (int e = 0; e < deg; e++) {
            int s = __ldg(col + beg + e);
            float w = (e < WCAP) ? s_w[warp][e]
                                 : __expf(lrelu(__ldg(asrc + s) + adv));
            float alpha = w * inv_den;
            float2 v = __ldg((const float2*)(h2 + (size_t)s * 64) + lane);
            acc.x += alpha * v.x; acc.y += alpha * v.y;
        }
    }
    float o0 = elu(acc.x + __ldg(b2 + lane * 2));
    float o1 = elu(acc.y + __ldg(b2 + lane * 2 + 1));
    *(float2*)(out + (size_t)d * 64 + lane * 2) = make_float2(o0, o1);
    float sc = o0 * __ldg(Ws + lane * 2) + o1 * __ldg(Ws + lane * 2 + 1);
#pragma unroll
    for (int off = 16; off; off >>= 1) sc += __shfl_xor_sync(0xffffffffu, sc, off);
    if (lane == 0) out[(size_t)N * 64 + d] = sc + __ldg(bs);
}

// ---------------------------------------------------------------------------
// Launch
// ---------------------------------------------------------------------------
extern "C" void kernel_launch(void* const* d_in, const int* in_sizes, int n_in,
                              void* d_out, int out_size)
{
    const float* x   = (const float*)d_in[0];
    const int*   ei  = (const int*)d_in[1];
    const float* W1  = (const float*)d_in[2];
    const float* as1 = (const float*)d_in[3];
    const float* ad1 = (const float*)d_in[4];
    const float* b1  = (const float*)d_in[5];
    const float* W2  = (const float*)d_in[6];
    const float* as2 = (const float*)d_in[7];
    const float* ad2 = (const float*)d_in[8];
    const float* b2  = (const float*)d_in[9];
    const float* Ws  = (const float*)d_in[10];
    const float* bs  = (const float*)d_in[11];
    float*       out = (float*)d_out;

    const int N = in_sizes[0] / 128;
    const int E = in_sizes[1] / 2;

    float *h1, *hm, *h2, *w1t, *w2t, *as1p, *ad1p, *as2p, *ad2p;
    int *cnt, *rp, *cur, *colp;
    cudaGetSymbolAddress((void**)&h1,   g_h1);
    cudaGetSymbolAddress((void**)&hm,   g_hm);
    cudaGetSymbolAddress((void**)&h2,   g_h2);
    cudaGetSymbolAddress((void**)&w1t,  g_w1t);
    cudaGetSymbolAddress((void**)&w2t,  g_w2t);
    cudaGetSymbolAddress((void**)&as1p, g_as1);
    cudaGetSymbolAddress((void**)&ad1p, g_ad1);
    cudaGetSymbolAddress((void**)&as2p, g_as2);
    cudaGetSymbolAddress((void**)&ad2p, g_ad2);
    cudaGetSymbolAddress((void**)&cnt,  g_cnt);
    cudaGetSymbolAddress((void**)&rp,   g_rp);
    cudaGetSymbolAddress((void**)&cur,  g_cur);
    cudaGetSymbolAddress((void**)&colp, g_col);

    static cudaStream_t s2 = nullptr;
    static cudaEvent_t evFork = nullptr, evJoin = nullptr;
    static bool attrSet = false;
    if (!s2) {
        cudaStreamCreateWithFlags(&s2, cudaStreamNonBlocking);
        cudaEventCreateWithFlags(&evFork, cudaEventDisableTiming);
        cudaEventCreateWithFlags(&evJoin, cudaEventDisableTiming);
    }
    if (!attrSet) {
        cudaFuncSetAttribute(tf32_gemm<true>,
                             cudaFuncAttributeMaxDynamicSharedMemorySize, GEMM_SMEM);
        cudaFuncSetAttribute(tf32_gemm<false>,
                             cudaFuncAttributeMaxDynamicSharedMemorySize, GEMM_SMEM);
        attrSet = true;
    }

    // Fork: CSR build on s2, concurrent with weight cvt + layer-1 GEMM.
    cudaEventRecord(evFork, 0);
    cudaStreamWaitEvent(s2, evFork, 0);
    cudaMemsetAsync(cnt, 0, (size_t)N * sizeof(int), s2);
    count_kernel<<<(E + 255) / 256, 256, 0, s2>>>(ei, cnt, E);
    scan_kernel<<<1, 1024, 0, s2>>>(cnt, rp, cur, N);
    fill_kernel<<<(E + 255) / 256, 256, 0, s2>>>(ei, cur, colp, E);
    cudaEventRecord(evJoin, s2);

    // Pre-round weights only (small); x is converted inside GEMM1 (CVTA).
    cvt_w_kernel<<<96, 256>>>(W1, w1t, 128 * 256 / 4, W2, w2t, 256 * 64 / 4);

    // Layer 1 GEMM (+fused att scalars); A = raw x, rounded in-kernel.
    tf32_gemm<true><<<dim3(4, (N + 127) / 128), 256, GEMM_SMEM>>>(
        N, 256, 128, x, w1t, h1, as1, ad1, as1p, ad1p, 4);

    cudaStreamWaitEvent(0, evJoin, 0);
    gather1_kernel<<<(N + 7) / 8, 256>>>(rp, colp, h1, as1p, ad1p, b1, hm, N);

    // Layer 2: hm already tf32-rounded by gather1.
    tf32_gemm<false><<<dim3(1, (N + 127) / 128), 256, GEMM_SMEM>>>(
        N, 64, 256, hm, w2t, h2, as2, ad2, as2p, ad2p, 1);
    gather2_kernel<<<(N + 7) / 8, 256>>>(rp, colp, h2, as2p, ad2p, b2, Ws, bs, out, N);
}